// round 2
// baseline (speedup 1.0000x reference)
#include <cuda_runtime.h>

#define N_NODES 30000
#define N_EDGES 480000

// ---------------------------------------------------------------------------
// Scratch (static device globals — no allocation)
// y layout per node: [l-block][m][ch(8)]  -> l=0 at off 0 (1*8), l=1 at off 8
// (3*8), l=2 at off 32 (5*8). ch = e*4 + c  (edge-channel major, matches
// reshape in reference). 72 floats per node.
// ---------------------------------------------------------------------------
__device__ __align__(16) float g_ybuf[N_NODES * 72];

// CG[l1][l2][lo] dense 5x5x5 pad: index ((l1*3+l2)*3+lo)*125 + (m*5+p)*5 + q
__device__ float g_cg[27 * 125];

// ---------------------------------------------------------------------------
// Kernel 1: zero y accumulator
// ---------------------------------------------------------------------------
__global__ void zero_kernel() {
    int i = blockIdx.x * blockDim.x + threadIdx.x;
    if (i < N_NODES * 18) {
        ((float4*)g_ybuf)[i] = make_float4(0.f, 0.f, 0.f, 0.f);
    }
}

// ---------------------------------------------------------------------------
// Kernel 2: Clebsch-Gordan coefficients (deterministic, tiny)
// ---------------------------------------------------------------------------
__device__ double dfac(int n) {
    double r = 1.0;
    for (int i = 2; i <= n; i++) r *= (double)i;
    return r;
}

__device__ double cg_coeff(int j1, int m1, int j2, int m2, int j, int m) {
    if (m != m1 + m2) return 0.0;
    int dj = j1 - j2; if (dj < 0) dj = -dj;
    if (j < dj || j > j1 + j2) return 0.0;
    double pre = sqrt((2.0 * j + 1.0) * dfac(j + j1 - j2) * dfac(j - j1 + j2) *
                      dfac(j1 + j2 - j) / dfac(j1 + j2 + j + 1));
    pre *= sqrt(dfac(j + m) * dfac(j - m) * dfac(j1 - m1) * dfac(j1 + m1) *
                dfac(j2 - m2) * dfac(j2 + m2));
    double s = 0.0;
    for (int k = 0; k <= j1 + j2 - j; k++) {
        int d0 = k;
        int d1 = j1 + j2 - j - k;
        int d2 = j1 - m1 - k;
        int d3 = j2 + m2 - k;
        int d4 = j - j2 + m1 + k;
        int d5 = j - j1 - m2 + k;
        if (d0 < 0 || d1 < 0 || d2 < 0 || d3 < 0 || d4 < 0 || d5 < 0) continue;
        double den = dfac(d0) * dfac(d1) * dfac(d2) * dfac(d3) * dfac(d4) * dfac(d5);
        s += ((k & 1) ? -1.0 : 1.0) / den;
    }
    return pre * s;
}

__global__ void cg_init_kernel() {
    int combo = blockIdx.x;           // 0..26
    int l1 = combo / 9;
    int l2 = (combo / 3) % 3;
    int lo = combo % 3;
    int t = threadIdx.x;              // 0..124
    int m = t / 25, p = (t / 5) % 5, q = t % 5;
    float val = 0.f;
    if (m <= 2 * lo && p <= 2 * l1 && q <= 2 * l2) {
        val = (float)cg_coeff(l1, p - l1, l2, q - l2, lo, m - lo);
    }
    g_cg[combo * 125 + t] = val;
}

// ---------------------------------------------------------------------------
// Kernel 3: edge gather / outer-product / scatter-add (vector atomics)
// edge_idx is int32 (JAX x64 disabled: jnp.int64 request materializes int32)
// ---------------------------------------------------------------------------
__device__ __forceinline__ void red4(float* p, float a, float b, float c, float d) {
    asm volatile("red.global.add.v4.f32 [%0], {%1,%2,%3,%4};"
                 :: "l"(p), "f"(a), "f"(b), "f"(c), "f"(d) : "memory");
}

__global__ void edge_kernel(const float* __restrict__ x0,
                            const float* __restrict__ x1,
                            const float* __restrict__ x2,
                            const float* __restrict__ ev,
                            const int* __restrict__ eidx) {
    int e = blockIdx.x * blockDim.x + threadIdx.x;
    if (e >= N_EDGES) return;
    int src = eidx[e];
    int dst = eidx[N_EDGES + e];
    float2 ee = *(const float2*)(ev + 2 * e);
    float* yb = g_ybuf + (size_t)dst * 72;

    // l = 0 : 4 floats  (x0[n][c])
    {
        float4 a = *(const float4*)(x0 + (size_t)src * 4);
        red4(yb + 0, ee.x * a.x, ee.x * a.y, ee.x * a.z, ee.x * a.w);
        red4(yb + 4, ee.y * a.x, ee.y * a.y, ee.y * a.z, ee.y * a.w);
    }
    // l = 1 : 12 floats (x1[n][c][m], m fastest)
    {
        float v[12];
        const float4* p = (const float4*)(x1 + (size_t)src * 12);
        ((float4*)v)[0] = p[0];
        ((float4*)v)[1] = p[1];
        ((float4*)v)[2] = p[2];
#pragma unroll
        for (int m = 0; m < 3; m++) {
            red4(yb + 8 + m * 8,
                 ee.x * v[0 * 3 + m], ee.x * v[1 * 3 + m],
                 ee.x * v[2 * 3 + m], ee.x * v[3 * 3 + m]);
            red4(yb + 8 + m * 8 + 4,
                 ee.y * v[0 * 3 + m], ee.y * v[1 * 3 + m],
                 ee.y * v[2 * 3 + m], ee.y * v[3 * 3 + m]);
        }
    }
    // l = 2 : 20 floats (x2[n][c][m])
    {
        float v[20];
        const float4* p = (const float4*)(x2 + (size_t)src * 20);
        ((float4*)v)[0] = p[0];
        ((float4*)v)[1] = p[1];
        ((float4*)v)[2] = p[2];
        ((float4*)v)[3] = p[3];
        ((float4*)v)[4] = p[4];
#pragma unroll
        for (int m = 0; m < 5; m++) {
            red4(yb + 32 + m * 8,
                 ee.x * v[0 * 5 + m], ee.x * v[1 * 5 + m],
                 ee.x * v[2 * 5 + m], ee.x * v[3 * 5 + m]);
            red4(yb + 32 + m * 8 + 4,
                 ee.y * v[0 * 5 + m], ee.y * v[1 * 5 + m],
                 ee.y * v[2 * 5 + m], ee.y * v[3 * 5 + m]);
        }
    }
}

// ---------------------------------------------------------------------------
// Kernel 4: per-(node, o) CG products + SO(3) linear, factorized:
//   H[c][q] = sum_d W[(off + c*CB + d)*8 + o] * B[d,q]
//   P[p][q] = sum_c A[c,p] * H[c][q]
//   acc[m] += sum_pq CG[m,p,q] * P[p][q]
// ---------------------------------------------------------------------------
template <int L1, int L2, int LO, int CA, int CB>
__device__ __forceinline__ void path_fn(float* __restrict__ acc,
                                        const float* __restrict__ Ab, int Acs, int Aps,
                                        const float* __restrict__ Bb, int Bcs, int Bps,
                                        const float* __restrict__ Wp, int o) {
    constexpr int P = 2 * L1 + 1, Q = 2 * L2 + 1, M = 2 * LO + 1;
    const float* Cg = g_cg + ((L1 * 3 + L2) * 3 + LO) * 125;

    float H[CA][Q];
#pragma unroll
    for (int c = 0; c < CA; c++)
#pragma unroll
        for (int q = 0; q < Q; q++) H[c][q] = 0.f;

#pragma unroll
    for (int d = 0; d < CB; d++) {
        float Bq[Q];
#pragma unroll
        for (int q = 0; q < Q; q++) Bq[q] = Bb[d * Bcs + q * Bps];
#pragma unroll
        for (int c = 0; c < CA; c++) {
            float w = Wp[(c * CB + d) * 8 + o];
#pragma unroll
            for (int q = 0; q < Q; q++) H[c][q] = fmaf(w, Bq[q], H[c][q]);
        }
    }

#pragma unroll
    for (int p = 0; p < P; p++) {
        float Pq[Q];
#pragma unroll
        for (int q = 0; q < Q; q++) Pq[q] = 0.f;
#pragma unroll
        for (int c = 0; c < CA; c++) {
            float a = Ab[c * Acs + p * Aps];
#pragma unroll
            for (int q = 0; q < Q; q++) Pq[q] = fmaf(a, H[c][q], Pq[q]);
        }
#pragma unroll
        for (int m = 0; m < M; m++) {
            float s = acc[m];
#pragma unroll
            for (int q = 0; q < Q; q++) s = fmaf(Cg[(m * 5 + p) * 5 + q], Pq[q], s);
            acc[m] = s;
        }
    }
}

__global__ __launch_bounds__(256)
void node_kernel(const float* __restrict__ x0, const float* __restrict__ x1,
                 const float* __restrict__ x2,
                 const float* __restrict__ Wxx0, const float* __restrict__ Wxx1,
                 const float* __restrict__ Wxx2,
                 const float* __restrict__ Wyx0, const float* __restrict__ Wyx1,
                 const float* __restrict__ Wyx2,
                 const float* __restrict__ Wyy0, const float* __restrict__ Wyy1,
                 const float* __restrict__ Wyy2,
                 float* __restrict__ out) {
    int t = blockIdx.x * blockDim.x + threadIdx.x;
    if (t >= N_NODES * 8) return;
    int n = t >> 3;
    int o = t & 7;

    const float* yb = g_ybuf + (size_t)n * 72;
    const float* y0p = yb;        // (c,p): c*1 + p*8
    const float* y1p = yb + 8;
    const float* y2p = yb + 32;
    const float* x0n = x0 + (size_t)n * 4;   // (c,p): c*1 + p*1 (P=1)
    const float* x1n = x1 + (size_t)n * 12;  // (c,p): c*3 + p
    const float* x2n = x2 + (size_t)n * 20;  // (c,p): c*5 + p

    float acc0[1] = {0.f};
    float acc1[3] = {0.f, 0.f, 0.f};
    float acc2[5] = {0.f, 0.f, 0.f, 0.f, 0.f};

    // ---- y x y (CA=8, CB=8), weights W_yy ----
    path_fn<0,0,0,8,8>(acc0, y0p,1,8, y0p,1,8, Wyy0 + 0*64*8, o);
    path_fn<1,1,0,8,8>(acc0, y1p,1,8, y1p,1,8, Wyy0 + 1*64*8, o);
    path_fn<2,2,0,8,8>(acc0, y2p,1,8, y2p,1,8, Wyy0 + 2*64*8, o);

    path_fn<0,1,1,8,8>(acc1, y0p,1,8, y1p,1,8, Wyy1 + 0*64*8, o);
    path_fn<1,0,1,8,8>(acc1, y1p,1,8, y0p,1,8, Wyy1 + 1*64*8, o);
    path_fn<1,1,1,8,8>(acc1, y1p,1,8, y1p,1,8, Wyy1 + 2*64*8, o);
    path_fn<1,2,1,8,8>(acc1, y1p,1,8, y2p,1,8, Wyy1 + 3*64*8, o);
    path_fn<2,1,1,8,8>(acc1, y2p,1,8, y1p,1,8, Wyy1 + 4*64*8, o);
    path_fn<2,2,1,8,8>(acc1, y2p,1,8, y2p,1,8, Wyy1 + 5*64*8, o);

    path_fn<0,2,2,8,8>(acc2, y0p,1,8, y2p,1,8, Wyy2 + 0*64*8, o);
    path_fn<1,1,2,8,8>(acc2, y1p,1,8, y1p,1,8, Wyy2 + 1*64*8, o);
    path_fn<1,2,2,8,8>(acc2, y1p,1,8, y2p,1,8, Wyy2 + 2*64*8, o);
    path_fn<2,0,2,8,8>(acc2, y2p,1,8, y0p,1,8, Wyy2 + 3*64*8, o);
    path_fn<2,1,2,8,8>(acc2, y2p,1,8, y1p,1,8, Wyy2 + 4*64*8, o);
    path_fn<2,2,2,8,8>(acc2, y2p,1,8, y2p,1,8, Wyy2 + 5*64*8, o);

    // ---- y x x (CA=8, CB=4), weights W_yx ----
    path_fn<0,0,0,8,4>(acc0, y0p,1,8, x0n,1,1, Wyx0 + 0*32*8, o);
    path_fn<1,1,0,8,4>(acc0, y1p,1,8, x1n,3,1, Wyx0 + 1*32*8, o);
    path_fn<2,2,0,8,4>(acc0, y2p,1,8, x2n,5,1, Wyx0 + 2*32*8, o);

    path_fn<0,1,1,8,4>(acc1, y0p,1,8, x1n,3,1, Wyx1 + 0*32*8, o);
    path_fn<1,0,1,8,4>(acc1, y1p,1,8, x0n,1,1, Wyx1 + 1*32*8, o);
    path_fn<1,1,1,8,4>(acc1, y1p,1,8, x1n,3,1, Wyx1 + 2*32*8, o);
    path_fn<1,2,1,8,4>(acc1, y1p,1,8, x2n,5,1, Wyx1 + 3*32*8, o);
    path_fn<2,1,1,8,4>(acc1, y2p,1,8, x1n,3,1, Wyx1 + 4*32*8, o);
    path_fn<2,2,1,8,4>(acc1, y2p,1,8, x2n,5,1, Wyx1 + 5*32*8, o);

    path_fn<0,2,2,8,4>(acc2, y0p,1,8, x2n,5,1, Wyx2 + 0*32*8, o);
    path_fn<1,1,2,8,4>(acc2, y1p,1,8, x1n,3,1, Wyx2 + 1*32*8, o);
    path_fn<1,2,2,8,4>(acc2, y1p,1,8, x2n,5,1, Wyx2 + 2*32*8, o);
    path_fn<2,0,2,8,4>(acc2, y2p,1,8, x0n,1,1, Wyx2 + 3*32*8, o);
    path_fn<2,1,2,8,4>(acc2, y2p,1,8, x1n,3,1, Wyx2 + 4*32*8, o);
    path_fn<2,2,2,8,4>(acc2, y2p,1,8, x2n,5,1, Wyx2 + 5*32*8, o);

    // ---- x x x (CA=4, CB=4), weights W_xx ----
    path_fn<0,0,0,4,4>(acc0, x0n,1,1, x0n,1,1, Wxx0 + 0*16*8, o);
    path_fn<1,1,0,4,4>(acc0, x1n,3,1, x1n,3,1, Wxx0 + 1*16*8, o);
    path_fn<2,2,0,4,4>(acc0, x2n,5,1, x2n,5,1, Wxx0 + 2*16*8, o);

    path_fn<0,1,1,4,4>(acc1, x0n,1,1, x1n,3,1, Wxx1 + 0*16*8, o);
    path_fn<1,0,1,4,4>(acc1, x1n,3,1, x0n,1,1, Wxx1 + 1*16*8, o);
    path_fn<1,1,1,4,4>(acc1, x1n,3,1, x1n,3,1, Wxx1 + 2*16*8, o);
    path_fn<1,2,1,4,4>(acc1, x1n,3,1, x2n,5,1, Wxx1 + 3*16*8, o);
    path_fn<2,1,1,4,4>(acc1, x2n,5,1, x1n,3,1, Wxx1 + 4*16*8, o);
    path_fn<2,2,1,4,4>(acc1, x2n,5,1, x2n,5,1, Wxx1 + 5*16*8, o);

    path_fn<0,2,2,4,4>(acc2, x0n,1,1, x2n,5,1, Wxx2 + 0*16*8, o);
    path_fn<1,1,2,4,4>(acc2, x1n,3,1, x1n,3,1, Wxx2 + 1*16*8, o);
    path_fn<1,2,2,4,4>(acc2, x1n,3,1, x2n,5,1, Wxx2 + 2*16*8, o);
    path_fn<2,0,2,4,4>(acc2, x2n,5,1, x0n,1,1, Wxx2 + 3*16*8, o);
    path_fn<2,1,2,4,4>(acc2, x2n,5,1, x1n,3,1, Wxx2 + 4*16*8, o);
    path_fn<2,2,2,4,4>(acc2, x2n,5,1, x2n,5,1, Wxx2 + 5*16*8, o);

    // ---- write outputs: out0 [N,8,1] | out1 [N,8,3] | out2 [N,8,5] ----
    out[n * 8 + o] = acc0[0];
    float* o1 = out + 240000 + ((size_t)n * 8 + o) * 3;
    o1[0] = acc1[0]; o1[1] = acc1[1]; o1[2] = acc1[2];
    float* o2 = out + 960000 + ((size_t)n * 8 + o) * 5;
    o2[0] = acc2[0]; o2[1] = acc2[1]; o2[2] = acc2[2]; o2[3] = acc2[3]; o2[4] = acc2[4];
}

// ---------------------------------------------------------------------------
extern "C" void kernel_launch(void* const* d_in, const int* in_sizes, int n_in,
                              void* d_out, int out_size) {
    const float* x0   = (const float*)d_in[0];
    const float* x1   = (const float*)d_in[1];
    const float* x2   = (const float*)d_in[2];
    const float* ev   = (const float*)d_in[3];
    const float* Wxx0 = (const float*)d_in[4];
    const float* Wxx1 = (const float*)d_in[5];
    const float* Wxx2 = (const float*)d_in[6];
    const float* Wyx0 = (const float*)d_in[7];
    const float* Wyx1 = (const float*)d_in[8];
    const float* Wyx2 = (const float*)d_in[9];
    const float* Wyy0 = (const float*)d_in[10];
    const float* Wyy1 = (const float*)d_in[11];
    const float* Wyy2 = (const float*)d_in[12];
    const int* eidx   = (const int*)d_in[13];
    float* out = (float*)d_out;

    zero_kernel<<<(N_NODES * 18 + 255) / 256, 256>>>();
    cg_init_kernel<<<27, 125>>>();
    edge_kernel<<<(N_EDGES + 255) / 256, 256>>>(x0, x1, x2, ev, eidx);
    node_kernel<<<(N_NODES * 8 + 255) / 256, 256>>>(
        x0, x1, x2, Wxx0, Wxx1, Wxx2, Wyx0, Wyx1, Wyx2, Wyy0, Wyy1, Wyy2, out);
}

// round 4
// speedup vs baseline: 1.0412x; 1.0412x over previous
#include <cuda_runtime.h>

#define N_NODES 30000
#define N_EDGES 480000

// ---------------------------------------------------------------------------
// Scratch (static device globals — no allocation)
// y layout per node: [l-block][m][ch(8)] -> l=0 @0 (1*8), l=1 @8 (3*8),
// l=2 @32 (5*8). ch = e*4 + c. 72 floats per node.
// ---------------------------------------------------------------------------
__device__ __align__(16) float g_ybuf[N_NODES * 72];

// CG[l1][l2][lo] dense 5x5x5 pad: index ((l1*3+l2)*3+lo)*125 + (m*5+p)*5 + q
__device__ float g_cg[27 * 125];

// Transposed weights, o-major then d-major then c:
//   g_wt[toff + o*R + k*(CA*CB) + d*CA + c] = W[(k*CA*CB + c*CB + d)*8 + o]
// Table order: yy0,yy1,yy2,yx0,yx1,yx2,xx0,xx1,xx2
__device__ __align__(16) float g_wt[13440];

// ---------------------------------------------------------------------------
// Kernel 1: zero y accumulator
// ---------------------------------------------------------------------------
__global__ void zero_kernel() {
    int i = blockIdx.x * blockDim.x + threadIdx.x;
    if (i < N_NODES * 18) {
        ((float4*)g_ybuf)[i] = make_float4(0.f, 0.f, 0.f, 0.f);
    }
}

// ---------------------------------------------------------------------------
// Kernel 2: Clebsch-Gordan coefficients (deterministic, tiny)
// ---------------------------------------------------------------------------
__device__ double dfac(int n) {
    double r = 1.0;
    for (int i = 2; i <= n; i++) r *= (double)i;
    return r;
}

__device__ double cg_coeff(int j1, int m1, int j2, int m2, int j, int m) {
    if (m != m1 + m2) return 0.0;
    int dj = j1 - j2; if (dj < 0) dj = -dj;
    if (j < dj || j > j1 + j2) return 0.0;
    double pre = sqrt((2.0 * j + 1.0) * dfac(j + j1 - j2) * dfac(j - j1 + j2) *
                      dfac(j1 + j2 - j) / dfac(j1 + j2 + j + 1));
    pre *= sqrt(dfac(j + m) * dfac(j - m) * dfac(j1 - m1) * dfac(j1 + m1) *
                dfac(j2 - m2) * dfac(j2 + m2));
    double s = 0.0;
    for (int k = 0; k <= j1 + j2 - j; k++) {
        int d0 = k;
        int d1 = j1 + j2 - j - k;
        int d2 = j1 - m1 - k;
        int d3 = j2 + m2 - k;
        int d4 = j - j2 + m1 + k;
        int d5 = j - j1 - m2 + k;
        if (d0 < 0 || d1 < 0 || d2 < 0 || d3 < 0 || d4 < 0 || d5 < 0) continue;
        double den = dfac(d0) * dfac(d1) * dfac(d2) * dfac(d3) * dfac(d4) * dfac(d5);
        s += ((k & 1) ? -1.0 : 1.0) / den;
    }
    return pre * s;
}

__global__ void cg_init_kernel() {
    int combo = blockIdx.x;           // 0..26
    int l1 = combo / 9;
    int l2 = (combo / 3) % 3;
    int lo = combo % 3;
    int t = threadIdx.x;              // 0..124
    int m = t / 25, p = (t / 5) % 5, q = t % 5;
    float val = 0.f;
    if (m <= 2 * lo && p <= 2 * l1 && q <= 2 * l2) {
        val = (float)cg_coeff(l1, p - l1, l2, q - l2, lo, m - lo);
    }
    g_cg[combo * 125 + t] = val;
}

// ---------------------------------------------------------------------------
// Kernel 2b: transpose weight tables into g_wt (one launch, tiny)
// ---------------------------------------------------------------------------
__global__ void wt_init_kernel(const float* __restrict__ w0, const float* __restrict__ w1,
                               const float* __restrict__ w2, const float* __restrict__ w3,
                               const float* __restrict__ w4, const float* __restrict__ w5,
                               const float* __restrict__ w6, const float* __restrict__ w7,
                               const float* __restrict__ w8) {
    int t = blockIdx.x * blockDim.x + threadIdx.x;
    if (t >= 13440) return;
    const int toff[10] = {0, 1536, 4608, 7680, 8448, 9984, 11520, 11904, 12672, 13440};
    const int CAs[9] = {8, 8, 8, 8, 8, 8, 4, 4, 4};
    const int CBs[9] = {8, 8, 8, 4, 4, 4, 4, 4, 4};
    const float* srcs[9] = {w0, w1, w2, w3, w4, w5, w6, w7, w8};
    int T = 0;
    while (t >= toff[T + 1]) T++;
    int u = t - toff[T];
    int R = (toff[T + 1] - toff[T]) / 8;
    int o = u / R;
    int v = u % R;
    int CA = CAs[T], CB = CBs[T], r = CA * CB;
    int k = v / r, w = v % r;
    int d = w / CA, c = w % CA;
    g_wt[t] = srcs[T][(k * r + c * CB + d) * 8 + o];
}

// ---------------------------------------------------------------------------
// Kernel 3: edge gather / outer-product / scatter-add (vector atomics)
// edge_idx is int32 (JAX x64 disabled)
// ---------------------------------------------------------------------------
__device__ __forceinline__ void red4(float* p, float a, float b, float c, float d) {
    asm volatile("red.global.add.v4.f32 [%0], {%1,%2,%3,%4};"
                 :: "l"(p), "f"(a), "f"(b), "f"(c), "f"(d) : "memory");
}

__global__ void edge_kernel(const float* __restrict__ x0,
                            const float* __restrict__ x1,
                            const float* __restrict__ x2,
                            const float* __restrict__ ev,
                            const int* __restrict__ eidx) {
    int e = blockIdx.x * blockDim.x + threadIdx.x;
    if (e >= N_EDGES) return;
    int src = eidx[e];
    int dst = eidx[N_EDGES + e];
    float2 ee = *(const float2*)(ev + 2 * e);
    float* yb = g_ybuf + (size_t)dst * 72;

    {
        float4 a = *(const float4*)(x0 + (size_t)src * 4);
        red4(yb + 0, ee.x * a.x, ee.x * a.y, ee.x * a.z, ee.x * a.w);
        red4(yb + 4, ee.y * a.x, ee.y * a.y, ee.y * a.z, ee.y * a.w);
    }
    {
        float v[12];
        const float4* p = (const float4*)(x1 + (size_t)src * 12);
        ((float4*)v)[0] = p[0];
        ((float4*)v)[1] = p[1];
        ((float4*)v)[2] = p[2];
#pragma unroll
        for (int m = 0; m < 3; m++) {
            red4(yb + 8 + m * 8,
                 ee.x * v[0 * 3 + m], ee.x * v[1 * 3 + m],
                 ee.x * v[2 * 3 + m], ee.x * v[3 * 3 + m]);
            red4(yb + 8 + m * 8 + 4,
                 ee.y * v[0 * 3 + m], ee.y * v[1 * 3 + m],
                 ee.y * v[2 * 3 + m], ee.y * v[3 * 3 + m]);
        }
    }
    {
        float v[20];
        const float4* p = (const float4*)(x2 + (size_t)src * 20);
        ((float4*)v)[0] = p[0];
        ((float4*)v)[1] = p[1];
        ((float4*)v)[2] = p[2];
        ((float4*)v)[3] = p[3];
        ((float4*)v)[4] = p[4];
#pragma unroll
        for (int m = 0; m < 5; m++) {
            red4(yb + 32 + m * 8,
                 ee.x * v[0 * 5 + m], ee.x * v[1 * 5 + m],
                 ee.x * v[2 * 5 + m], ee.x * v[3 * 5 + m]);
            red4(yb + 32 + m * 8 + 4,
                 ee.y * v[0 * 5 + m], ee.y * v[1 * 5 + m],
                 ee.y * v[2 * 5 + m], ee.y * v[3 * 5 + m]);
        }
    }
}

// ---------------------------------------------------------------------------
// Kernel 4: per-(node, o) CG products + SO(3) linear.
// Features and CG staged in shared memory; weights read via transposed
// float4 layout. Per path:
//   H[c][q] = sum_d Wt[d*CA+c] * B[d,q]
//   Pq[q]   = sum_c A[c,p] * H[c][q]
//   acc[m] += sum_pq CG[m,p,q] * Pq[q]
// ---------------------------------------------------------------------------
template <int L1, int L2, int LO, int CA, int CB>
__device__ __forceinline__ void path_fn(float* __restrict__ acc,
                                        const float* __restrict__ sA, int Acs, int Aps,
                                        const float* __restrict__ sB, int Bcs, int Bps,
                                        const float* __restrict__ Wt,
                                        const float* __restrict__ sCG) {
    constexpr int P = 2 * L1 + 1, Q = 2 * L2 + 1, M = 2 * LO + 1;
    const float* Cg = sCG + ((L1 * 3 + L2) * 3 + LO) * 125;

    float H[CA][Q];
#pragma unroll
    for (int c = 0; c < CA; c++)
#pragma unroll
        for (int q = 0; q < Q; q++) H[c][q] = 0.f;

#pragma unroll
    for (int d = 0; d < CB; d++) {
        float Bq[Q];
#pragma unroll
        for (int q = 0; q < Q; q++) Bq[q] = sB[d * Bcs + q * Bps];
        float Wc[CA];
        const float4* w4 = (const float4*)(Wt + d * CA);
        ((float4*)Wc)[0] = w4[0];
        if (CA == 8) ((float4*)Wc)[1] = w4[1];
#pragma unroll
        for (int c = 0; c < CA; c++)
#pragma unroll
            for (int q = 0; q < Q; q++) H[c][q] = fmaf(Wc[c], Bq[q], H[c][q]);
    }

#pragma unroll
    for (int p = 0; p < P; p++) {
        float Pq[Q];
#pragma unroll
        for (int q = 0; q < Q; q++) Pq[q] = 0.f;
#pragma unroll
        for (int c = 0; c < CA; c++) {
            float a = sA[c * Acs + p * Aps];
#pragma unroll
            for (int q = 0; q < Q; q++) Pq[q] = fmaf(a, H[c][q], Pq[q]);
        }
#pragma unroll
        for (int m = 0; m < M; m++) {
            float s = acc[m];
#pragma unroll
            for (int q = 0; q < Q; q++) s = fmaf(Cg[(m * 5 + p) * 5 + q], Pq[q], s);
            acc[m] = s;
        }
    }
}

__global__ __launch_bounds__(256, 2)
void node_kernel(const float* __restrict__ x0, const float* __restrict__ x1,
                 const float* __restrict__ x2, float* __restrict__ out) {
    __shared__ float s_y[32 * 72];
    __shared__ float s_x[32 * 36];
    __shared__ float s_cg[27 * 125];

    int tid = threadIdx.x;
    int nblk = blockIdx.x * 32;

    // stage y: 32 nodes x 18 float4
    for (int i = tid; i < 32 * 18; i += 256) {
        int nl = i / 18, j = i % 18;
        int gn = nblk + nl;
        float4 v = make_float4(0.f, 0.f, 0.f, 0.f);
        if (gn < N_NODES) v = ((const float4*)(g_ybuf + (size_t)gn * 72))[j];
        ((float4*)(s_y + nl * 72))[j] = v;
    }
    // stage x: 32 nodes x 9 float4 (x0:1, x1:3, x2:5)
    for (int i = tid; i < 32 * 9; i += 256) {
        int nl = i / 9, j = i % 9;
        int gn = nblk + nl;
        float4 v = make_float4(0.f, 0.f, 0.f, 0.f);
        if (gn < N_NODES) {
            if (j == 0)      v = ((const float4*)(x0 + (size_t)gn * 4))[0];
            else if (j < 4)  v = ((const float4*)(x1 + (size_t)gn * 12))[j - 1];
            else             v = ((const float4*)(x2 + (size_t)gn * 20))[j - 4];
        }
        ((float4*)(s_x + nl * 36))[j] = v;
    }
    // stage CG table
    for (int i = tid; i < 27 * 125; i += 256) s_cg[i] = g_cg[i];
    __syncthreads();

    int nl = tid >> 3;
    int o = tid & 7;
    int n = nblk + nl;
    if (n >= N_NODES) return;

    const float* sy = s_y + nl * 72;
    const float* sx = s_x + nl * 36;
    const float* y0p = sy;        // (c,q): c*1 + q*8
    const float* y1p = sy + 8;
    const float* y2p = sy + 32;
    const float* x0n = sx;        // (c,q): c*1 + q*1
    const float* x1n = sx + 4;    // (c,q): c*3 + q
    const float* x2n = sx + 16;   // (c,q): c*5 + q

    // transposed weight table bases for this o
    const float* wyy0 = g_wt + 0     + o * 192;
    const float* wyy1 = g_wt + 1536  + o * 384;
    const float* wyy2 = g_wt + 4608  + o * 384;
    const float* wyx0 = g_wt + 7680  + o * 96;
    const float* wyx1 = g_wt + 8448  + o * 192;
    const float* wyx2 = g_wt + 9984  + o * 192;
    const float* wxx0 = g_wt + 11520 + o * 48;
    const float* wxx1 = g_wt + 11904 + o * 96;
    const float* wxx2 = g_wt + 12672 + o * 96;

    float acc0[1] = {0.f};
    float acc1[3] = {0.f, 0.f, 0.f};
    float acc2[5] = {0.f, 0.f, 0.f, 0.f, 0.f};

    // ---- y x y (CA=8, CB=8) ----
    path_fn<0,0,0,8,8>(acc0, y0p,1,8, y0p,1,8, wyy0 + 0*64, s_cg);
    path_fn<1,1,0,8,8>(acc0, y1p,1,8, y1p,1,8, wyy0 + 1*64, s_cg);
    path_fn<2,2,0,8,8>(acc0, y2p,1,8, y2p,1,8, wyy0 + 2*64, s_cg);

    path_fn<0,1,1,8,8>(acc1, y0p,1,8, y1p,1,8, wyy1 + 0*64, s_cg);
    path_fn<1,0,1,8,8>(acc1, y1p,1,8, y0p,1,8, wyy1 + 1*64, s_cg);
    path_fn<1,1,1,8,8>(acc1, y1p,1,8, y1p,1,8, wyy1 + 2*64, s_cg);
    path_fn<1,2,1,8,8>(acc1, y1p,1,8, y2p,1,8, wyy1 + 3*64, s_cg);
    path_fn<2,1,1,8,8>(acc1, y2p,1,8, y1p,1,8, wyy1 + 4*64, s_cg);
    path_fn<2,2,1,8,8>(acc1, y2p,1,8, y2p,1,8, wyy1 + 5*64, s_cg);

    path_fn<0,2,2,8,8>(acc2, y0p,1,8, y2p,1,8, wyy2 + 0*64, s_cg);
    path_fn<1,1,2,8,8>(acc2, y1p,1,8, y1p,1,8, wyy2 + 1*64, s_cg);
    path_fn<1,2,2,8,8>(acc2, y1p,1,8, y2p,1,8, wyy2 + 2*64, s_cg);
    path_fn<2,0,2,8,8>(acc2, y2p,1,8, y0p,1,8, wyy2 + 3*64, s_cg);
    path_fn<2,1,2,8,8>(acc2, y2p,1,8, y1p,1,8, wyy2 + 4*64, s_cg);
    path_fn<2,2,2,8,8>(acc2, y2p,1,8, y2p,1,8, wyy2 + 5*64, s_cg);

    // ---- y x x (CA=8, CB=4) ----
    path_fn<0,0,0,8,4>(acc0, y0p,1,8, x0n,1,1, wyx0 + 0*32, s_cg);
    path_fn<1,1,0,8,4>(acc0, y1p,1,8, x1n,3,1, wyx0 + 1*32, s_cg);
    path_fn<2,2,0,8,4>(acc0, y2p,1,8, x2n,5,1, wyx0 + 2*32, s_cg);

    path_fn<0,1,1,8,4>(acc1, y0p,1,8, x1n,3,1, wyx1 + 0*32, s_cg);
    path_fn<1,0,1,8,4>(acc1, y1p,1,8, x0n,1,1, wyx1 + 1*32, s_cg);
    path_fn<1,1,1,8,4>(acc1, y1p,1,8, x1n,3,1, wyx1 + 2*32, s_cg);
    path_fn<1,2,1,8,4>(acc1, y1p,1,8, x2n,5,1, wyx1 + 3*32, s_cg);
    path_fn<2,1,1,8,4>(acc1, y2p,1,8, x1n,3,1, wyx1 + 4*32, s_cg);
    path_fn<2,2,1,8,4>(acc1, y2p,1,8, x2n,5,1, wyx1 + 5*32, s_cg);

    path_fn<0,2,2,8,4>(acc2, y0p,1,8, x2n,5,1, wyx2 + 0*32, s_cg);
    path_fn<1,1,2,8,4>(acc2, y1p,1,8, x1n,3,1, wyx2 + 1*32, s_cg);
    path_fn<1,2,2,8,4>(acc2, y1p,1,8, x2n,5,1, wyx2 + 2*32, s_cg);
    path_fn<2,0,2,8,4>(acc2, y2p,1,8, x0n,1,1, wyx2 + 3*32, s_cg);
    path_fn<2,1,2,8,4>(acc2, y2p,1,8, x1n,3,1, wyx2 + 4*32, s_cg);
    path_fn<2,2,2,8,4>(acc2, y2p,1,8, x2n,5,1, wyx2 + 5*32, s_cg);

    // ---- x x x (CA=4, CB=4) ----
    path_fn<0,0,0,4,4>(acc0, x0n,1,1, x0n,1,1, wxx0 + 0*16, s_cg);
    path_fn<1,1,0,4,4>(acc0, x1n,3,1, x1n,3,1, wxx0 + 1*16, s_cg);
    path_fn<2,2,0,4,4>(acc0, x2n,5,1, x2n,5,1, wxx0 + 2*16, s_cg);

    path_fn<0,1,1,4,4>(acc1, x0n,1,1, x1n,3,1, wxx1 + 0*16, s_cg);
    path_fn<1,0,1,4,4>(acc1, x1n,3,1, x0n,1,1, wxx1 + 1*16, s_cg);
    path_fn<1,1,1,4,4>(acc1, x1n,3,1, x1n,3,1, wxx1 + 2*16, s_cg);
    path_fn<1,2,1,4,4>(acc1, x1n,3,1, x2n,5,1, wxx1 + 3*16, s_cg);
    path_fn<2,1,1,4,4>(acc1, x2n,5,1, x1n,3,1, wxx1 + 4*16, s_cg);
    path_fn<2,2,1,4,4>(acc1, x2n,5,1, x2n,5,1, wxx1 + 5*16, s_cg);

    path_fn<0,2,2,4,4>(acc2, x0n,1,1, x2n,5,1, wxx2 + 0*16, s_cg);
    path_fn<1,1,2,4,4>(acc2, x1n,3,1, x1n,3,1, wxx2 + 1*16, s_cg);
    path_fn<1,2,2,4,4>(acc2, x1n,3,1, x2n,5,1, wxx2 + 2*16, s_cg);
    path_fn<2,0,2,4,4>(acc2, x2n,5,1, x0n,1,1, wxx2 + 3*16, s_cg);
    path_fn<2,1,2,4,4>(acc2, x2n,5,1, x1n,3,1, wxx2 + 4*16, s_cg);
    path_fn<2,2,2,4,4>(acc2, x2n,5,1, x2n,5,1, wxx2 + 5*16, s_cg);

    // ---- outputs: out0 [N,8,1] | out1 [N,8,3] | out2 [N,8,5] ----
    out[n * 8 + o] = acc0[0];
    float* o1 = out + 240000 + ((size_t)n * 8 + o) * 3;
    o1[0] = acc1[0]; o1[1] = acc1[1]; o1[2] = acc1[2];
    float* o2 = out + 960000 + ((size_t)n * 8 + o) * 5;
    o2[0] = acc2[0]; o2[1] = acc2[1]; o2[2] = acc2[2]; o2[3] = acc2[3]; o2[4] = acc2[4];
}

// ---------------------------------------------------------------------------
extern "C" void kernel_launch(void* const* d_in, const int* in_sizes, int n_in,
                              void* d_out, int out_size) {
    const float* x0   = (const float*)d_in[0];
    const float* x1   = (const float*)d_in[1];
    const float* x2   = (const float*)d_in[2];
    const float* ev   = (const float*)d_in[3];
    const float* Wxx0 = (const float*)d_in[4];
    const float* Wxx1 = (const float*)d_in[5];
    const float* Wxx2 = (const float*)d_in[6];
    const float* Wyx0 = (const float*)d_in[7];
    const float* Wyx1 = (const float*)d_in[8];
    const float* Wyx2 = (const float*)d_in[9];
    const float* Wyy0 = (const float*)d_in[10];
    const float* Wyy1 = (const float*)d_in[11];
    const float* Wyy2 = (const float*)d_in[12];
    const int* eidx   = (const int*)d_in[13];
    float* out = (float*)d_out;

    zero_kernel<<<(N_NODES * 18 + 255) / 256, 256>>>();
    cg_init_kernel<<<27, 125>>>();
    wt_init_kernel<<<(13440 + 255) / 256, 256>>>(Wyy0, Wyy1, Wyy2,
                                                 Wyx0, Wyx1, Wyx2,
                                                 Wxx0, Wxx1, Wxx2);
    edge_kernel<<<(N_EDGES + 255) / 256, 256>>>(x0, x1, x2, ev, eidx);
    node_kernel<<<(N_NODES + 31) / 32, 256>>>(x0, x1, x2, out);
}

// round 5
// speedup vs baseline: 2.2216x; 2.1337x over previous
#include <cuda_runtime.h>

#define N_NODES 30000
#define N_EDGES 480000

// ---------------------------------------------------------------------------
// Scratch (static device globals — no allocation)
// y layout per node: [l-block][m][ch(8)] -> l=0 @0 (1*8), l=1 @8 (3*8),
// l=2 @32 (5*8). ch = e*4 + c. 72 floats per node.
// ---------------------------------------------------------------------------
__device__ __align__(16) float g_ybuf[N_NODES * 72];

// Compacted CG (selection rule m = (p-l1)+(q-l2)+lo):
// g_cg2[combo*25 + p*5 + q] = C[m(p,q), p, q]  (0 if out of range)
__device__ float g_cg2[27 * 25];

// Transposed weights, o-major then d-major then c:
//   g_wt[toff + o*R + k*(CA*CB) + d*CA + c] = W[(k*CA*CB + c*CB + d)*8 + o]
// Table order: yy0,yy1,yy2,yx0,yx1,yx2,xx0,xx1,xx2
__device__ __align__(16) float g_wt[13440];

// ---------------------------------------------------------------------------
// Kernel 1: zero y accumulator
// ---------------------------------------------------------------------------
__global__ void zero_kernel() {
    int i = blockIdx.x * blockDim.x + threadIdx.x;
    if (i < N_NODES * 18) {
        ((float4*)g_ybuf)[i] = make_float4(0.f, 0.f, 0.f, 0.f);
    }
}

// ---------------------------------------------------------------------------
// Kernel 2: Clebsch-Gordan coefficients (deterministic, tiny)
// ---------------------------------------------------------------------------
__device__ double dfac(int n) {
    double r = 1.0;
    for (int i = 2; i <= n; i++) r *= (double)i;
    return r;
}

__device__ double cg_coeff(int j1, int m1, int j2, int m2, int j, int m) {
    if (m != m1 + m2) return 0.0;
    int dj = j1 - j2; if (dj < 0) dj = -dj;
    if (j < dj || j > j1 + j2) return 0.0;
    double pre = sqrt((2.0 * j + 1.0) * dfac(j + j1 - j2) * dfac(j - j1 + j2) *
                      dfac(j1 + j2 - j) / dfac(j1 + j2 + j + 1));
    pre *= sqrt(dfac(j + m) * dfac(j - m) * dfac(j1 - m1) * dfac(j1 + m1) *
                dfac(j2 - m2) * dfac(j2 + m2));
    double s = 0.0;
    for (int k = 0; k <= j1 + j2 - j; k++) {
        int d0 = k;
        int d1 = j1 + j2 - j - k;
        int d2 = j1 - m1 - k;
        int d3 = j2 + m2 - k;
        int d4 = j - j2 + m1 + k;
        int d5 = j - j1 - m2 + k;
        if (d0 < 0 || d1 < 0 || d2 < 0 || d3 < 0 || d4 < 0 || d5 < 0) continue;
        double den = dfac(d0) * dfac(d1) * dfac(d2) * dfac(d3) * dfac(d4) * dfac(d5);
        s += ((k & 1) ? -1.0 : 1.0) / den;
    }
    return pre * s;
}

__global__ void cg_init_kernel() {
    int combo = blockIdx.x;           // 0..26
    int l1 = combo / 9;
    int l2 = (combo / 3) % 3;
    int lo = combo % 3;
    int t = threadIdx.x;              // 0..24
    int p = t / 5, q = t % 5;
    int m = (p - l1) + (q - l2) + lo; // selection rule
    float val = 0.f;
    if (p <= 2 * l1 && q <= 2 * l2 && m >= 0 && m <= 2 * lo) {
        val = (float)cg_coeff(l1, p - l1, l2, q - l2, lo, m - lo);
    }
    g_cg2[combo * 25 + t] = val;
}

// ---------------------------------------------------------------------------
// Kernel 2b: transpose weight tables into g_wt (one launch, tiny)
// ---------------------------------------------------------------------------
__global__ void wt_init_kernel(const float* __restrict__ w0, const float* __restrict__ w1,
                               const float* __restrict__ w2, const float* __restrict__ w3,
                               const float* __restrict__ w4, const float* __restrict__ w5,
                               const float* __restrict__ w6, const float* __restrict__ w7,
                               const float* __restrict__ w8) {
    int t = blockIdx.x * blockDim.x + threadIdx.x;
    if (t >= 13440) return;
    const int toff[10] = {0, 1536, 4608, 7680, 8448, 9984, 11520, 11904, 12672, 13440};
    const int CAs[9] = {8, 8, 8, 8, 8, 8, 4, 4, 4};
    const int CBs[9] = {8, 8, 8, 4, 4, 4, 4, 4, 4};
    const float* srcs[9] = {w0, w1, w2, w3, w4, w5, w6, w7, w8};
    int T = 0;
    while (t >= toff[T + 1]) T++;
    int u = t - toff[T];
    int R = (toff[T + 1] - toff[T]) / 8;
    int o = u / R;
    int v = u % R;
    int CA = CAs[T], CB = CBs[T], r = CA * CB;
    int k = v / r, w = v % r;
    int d = w / CA, c = w % CA;
    g_wt[t] = srcs[T][(k * r + c * CB + d) * 8 + o];
}

// ---------------------------------------------------------------------------
// Kernel 3: edge gather / outer-product / scatter-add (vector atomics)
// edge_idx is int32 (JAX x64 disabled)
// ---------------------------------------------------------------------------
__device__ __forceinline__ void red4(float* p, float a, float b, float c, float d) {
    asm volatile("red.global.add.v4.f32 [%0], {%1,%2,%3,%4};"
                 :: "l"(p), "f"(a), "f"(b), "f"(c), "f"(d) : "memory");
}

__global__ void edge_kernel(const float* __restrict__ x0,
                            const float* __restrict__ x1,
                            const float* __restrict__ x2,
                            const float* __restrict__ ev,
                            const int* __restrict__ eidx) {
    int e = blockIdx.x * blockDim.x + threadIdx.x;
    if (e >= N_EDGES) return;
    int src = eidx[e];
    int dst = eidx[N_EDGES + e];
    float2 ee = *(const float2*)(ev + 2 * e);
    float* yb = g_ybuf + (size_t)dst * 72;

    {
        float4 a = *(const float4*)(x0 + (size_t)src * 4);
        red4(yb + 0, ee.x * a.x, ee.x * a.y, ee.x * a.z, ee.x * a.w);
        red4(yb + 4, ee.y * a.x, ee.y * a.y, ee.y * a.z, ee.y * a.w);
    }
    {
        float v[12];
        const float4* p = (const float4*)(x1 + (size_t)src * 12);
        ((float4*)v)[0] = p[0];
        ((float4*)v)[1] = p[1];
        ((float4*)v)[2] = p[2];
#pragma unroll
        for (int m = 0; m < 3; m++) {
            red4(yb + 8 + m * 8,
                 ee.x * v[0 * 3 + m], ee.x * v[1 * 3 + m],
                 ee.x * v[2 * 3 + m], ee.x * v[3 * 3 + m]);
            red4(yb + 8 + m * 8 + 4,
                 ee.y * v[0 * 3 + m], ee.y * v[1 * 3 + m],
                 ee.y * v[2 * 3 + m], ee.y * v[3 * 3 + m]);
        }
    }
    {
        float v[20];
        const float4* p = (const float4*)(x2 + (size_t)src * 20);
        ((float4*)v)[0] = p[0];
        ((float4*)v)[1] = p[1];
        ((float4*)v)[2] = p[2];
        ((float4*)v)[3] = p[3];
        ((float4*)v)[4] = p[4];
#pragma unroll
        for (int m = 0; m < 5; m++) {
            red4(yb + 32 + m * 8,
                 ee.x * v[0 * 5 + m], ee.x * v[1 * 5 + m],
                 ee.x * v[2 * 5 + m], ee.x * v[3 * 5 + m]);
            red4(yb + 32 + m * 8 + 4,
                 ee.y * v[0 * 5 + m], ee.y * v[1 * 5 + m],
                 ee.y * v[2 * 5 + m], ee.y * v[3 * 5 + m]);
        }
    }
}

// ---------------------------------------------------------------------------
// Kernel 4: per-(node, o) CG products + SO(3) linear.
// Warp layout: warp w -> o = w; lane l -> node (32 nodes/block).
// W loads are warp-uniform; feature LDS are conflict-free (padded strides).
// Per path:
//   H[c][q]   = sum_d Wt[d*CA+c] * B[d,q]
//   Pq[q]     = sum_c A[c,p] * H[c][q]
//   acc[m(p,q)] += CG2[p,q] * Pq[q]   (selection rule: one m per (p,q))
// ---------------------------------------------------------------------------
template <int L1, int L2, int LO, int CA, int CB>
__device__ __forceinline__ void path_fn(float* __restrict__ acc,
                                        const float* __restrict__ sA, int Acs, int Aps,
                                        const float* __restrict__ sB, int Bcs, int Bps,
                                        const float* __restrict__ Wt,
                                        const float* __restrict__ sCG2) {
    constexpr int P = 2 * L1 + 1, Q = 2 * L2 + 1, M = 2 * LO + 1;
    const float* Cg = sCG2 + ((L1 * 3 + L2) * 3 + LO) * 25;

    float H[CA][Q];
#pragma unroll
    for (int c = 0; c < CA; c++)
#pragma unroll
        for (int q = 0; q < Q; q++) H[c][q] = 0.f;

#pragma unroll
    for (int d = 0; d < CB; d++) {
        float Bq[Q];
#pragma unroll
        for (int q = 0; q < Q; q++) Bq[q] = sB[d * Bcs + q * Bps];
        float Wc[CA];
        const float4* w4 = (const float4*)(Wt + d * CA);
        ((float4*)Wc)[0] = w4[0];
        if (CA == 8) ((float4*)Wc)[1] = w4[1];
#pragma unroll
        for (int c = 0; c < CA; c++)
#pragma unroll
            for (int q = 0; q < Q; q++) H[c][q] = fmaf(Wc[c], Bq[q], H[c][q]);
    }

#pragma unroll
    for (int p = 0; p < P; p++) {
        float Pq[Q];
#pragma unroll
        for (int q = 0; q < Q; q++) Pq[q] = 0.f;
#pragma unroll
        for (int c = 0; c < CA; c++) {
            float a = sA[c * Acs + p * Aps];
#pragma unroll
            for (int q = 0; q < Q; q++) Pq[q] = fmaf(a, H[c][q], Pq[q]);
        }
#pragma unroll
        for (int q = 0; q < Q; q++) {
            constexpr int base = LO - L1 - L2;  // m = p+q+base
            int mi = p + q + base;
            if (mi >= 0 && mi < M) acc[mi] = fmaf(Cg[p * 5 + q], Pq[q], acc[mi]);
        }
    }
}

#define SY_STRIDE 73
#define SX_STRIDE 37

__global__ __launch_bounds__(256, 2)
void node_kernel(const float* __restrict__ x0, const float* __restrict__ x1,
                 const float* __restrict__ x2, float* __restrict__ out) {
    __shared__ float s_y[32 * SY_STRIDE];
    __shared__ float s_x[32 * SX_STRIDE];
    __shared__ float s_cg[27 * 25];

    int tid = threadIdx.x;
    int nblk = blockIdx.x * 32;

    // stage y: 32 nodes x 72 floats (padded stride)
    for (int i = tid; i < 32 * 72; i += 256) {
        int nl = i / 72, j = i % 72;
        int gn = nblk + nl;
        s_y[nl * SY_STRIDE + j] = (gn < N_NODES) ? g_ybuf[(size_t)gn * 72 + j] : 0.f;
    }
    // stage x: 32 nodes x 36 floats (x0:4, x1:12, x2:20), padded stride
    for (int i = tid; i < 32 * 36; i += 256) {
        int nl = i / 36, j = i % 36;
        int gn = nblk + nl;
        float v = 0.f;
        if (gn < N_NODES) {
            if (j < 4)       v = x0[(size_t)gn * 4 + j];
            else if (j < 16) v = x1[(size_t)gn * 12 + (j - 4)];
            else             v = x2[(size_t)gn * 20 + (j - 16)];
        }
        s_x[nl * SX_STRIDE + j] = v;
    }
    // stage compact CG table
    for (int i = tid; i < 27 * 25; i += 256) s_cg[i] = g_cg2[i];
    __syncthreads();

    int nl = tid & 31;      // lane -> node
    int o = tid >> 5;       // warp -> output channel
    int n = nblk + nl;
    if (n >= N_NODES) return;

    const float* sy = s_y + nl * SY_STRIDE;
    const float* sx = s_x + nl * SX_STRIDE;
    const float* y0p = sy;        // (c,q): c*1 + q*8
    const float* y1p = sy + 8;
    const float* y2p = sy + 32;
    const float* x0n = sx;        // (c,q): c*1 + q*1
    const float* x1n = sx + 4;    // (c,q): c*3 + q
    const float* x2n = sx + 16;   // (c,q): c*5 + q

    // transposed weight table bases for this o (warp-uniform)
    const float* wyy0 = g_wt + 0     + o * 192;
    const float* wyy1 = g_wt + 1536  + o * 384;
    const float* wyy2 = g_wt + 4608  + o * 384;
    const float* wyx0 = g_wt + 7680  + o * 96;
    const float* wyx1 = g_wt + 8448  + o * 192;
    const float* wyx2 = g_wt + 9984  + o * 192;
    const float* wxx0 = g_wt + 11520 + o * 48;
    const float* wxx1 = g_wt + 11904 + o * 96;
    const float* wxx2 = g_wt + 12672 + o * 96;

    float acc0[1] = {0.f};
    float acc1[3] = {0.f, 0.f, 0.f};
    float acc2[5] = {0.f, 0.f, 0.f, 0.f, 0.f};

    // ---- y x y (CA=8, CB=8) ----
    path_fn<0,0,0,8,8>(acc0, y0p,1,8, y0p,1,8, wyy0 + 0*64, s_cg);
    path_fn<1,1,0,8,8>(acc0, y1p,1,8, y1p,1,8, wyy0 + 1*64, s_cg);
    path_fn<2,2,0,8,8>(acc0, y2p,1,8, y2p,1,8, wyy0 + 2*64, s_cg);

    path_fn<0,1,1,8,8>(acc1, y0p,1,8, y1p,1,8, wyy1 + 0*64, s_cg);
    path_fn<1,0,1,8,8>(acc1, y1p,1,8, y0p,1,8, wyy1 + 1*64, s_cg);
    path_fn<1,1,1,8,8>(acc1, y1p,1,8, y1p,1,8, wyy1 + 2*64, s_cg);
    path_fn<1,2,1,8,8>(acc1, y1p,1,8, y2p,1,8, wyy1 + 3*64, s_cg);
    path_fn<2,1,1,8,8>(acc1, y2p,1,8, y1p,1,8, wyy1 + 4*64, s_cg);
    path_fn<2,2,1,8,8>(acc1, y2p,1,8, y2p,1,8, wyy1 + 5*64, s_cg);

    path_fn<0,2,2,8,8>(acc2, y0p,1,8, y2p,1,8, wyy2 + 0*64, s_cg);
    path_fn<1,1,2,8,8>(acc2, y1p,1,8, y1p,1,8, wyy2 + 1*64, s_cg);
    path_fn<1,2,2,8,8>(acc2, y1p,1,8, y2p,1,8, wyy2 + 2*64, s_cg);
    path_fn<2,0,2,8,8>(acc2, y2p,1,8, y0p,1,8, wyy2 + 3*64, s_cg);
    path_fn<2,1,2,8,8>(acc2, y2p,1,8, y1p,1,8, wyy2 + 4*64, s_cg);
    path_fn<2,2,2,8,8>(acc2, y2p,1,8, y2p,1,8, wyy2 + 5*64, s_cg);

    // ---- y x x (CA=8, CB=4) ----
    path_fn<0,0,0,8,4>(acc0, y0p,1,8, x0n,1,1, wyx0 + 0*32, s_cg);
    path_fn<1,1,0,8,4>(acc0, y1p,1,8, x1n,3,1, wyx0 + 1*32, s_cg);
    path_fn<2,2,0,8,4>(acc0, y2p,1,8, x2n,5,1, wyx0 + 2*32, s_cg);

    path_fn<0,1,1,8,4>(acc1, y0p,1,8, x1n,3,1, wyx1 + 0*32, s_cg);
    path_fn<1,0,1,8,4>(acc1, y1p,1,8, x0n,1,1, wyx1 + 1*32, s_cg);
    path_fn<1,1,1,8,4>(acc1, y1p,1,8, x1n,3,1, wyx1 + 2*32, s_cg);
    path_fn<1,2,1,8,4>(acc1, y1p,1,8, x2n,5,1, wyx1 + 3*32, s_cg);
    path_fn<2,1,1,8,4>(acc1, y2p,1,8, x1n,3,1, wyx1 + 4*32, s_cg);
    path_fn<2,2,1,8,4>(acc1, y2p,1,8, x2n,5,1, wyx1 + 5*32, s_cg);

    path_fn<0,2,2,8,4>(acc2, y0p,1,8, x2n,5,1, wyx2 + 0*32, s_cg);
    path_fn<1,1,2,8,4>(acc2, y1p,1,8, x1n,3,1, wyx2 + 1*32, s_cg);
    path_fn<1,2,2,8,4>(acc2, y1p,1,8, x2n,5,1, wyx2 + 2*32, s_cg);
    path_fn<2,0,2,8,4>(acc2, y2p,1,8, x0n,1,1, wyx2 + 3*32, s_cg);
    path_fn<2,1,2,8,4>(acc2, y2p,1,8, x1n,3,1, wyx2 + 4*32, s_cg);
    path_fn<2,2,2,8,4>(acc2, y2p,1,8, x2n,5,1, wyx2 + 5*32, s_cg);

    // ---- x x x (CA=4, CB=4) ----
    path_fn<0,0,0,4,4>(acc0, x0n,1,1, x0n,1,1, wxx0 + 0*16, s_cg);
    path_fn<1,1,0,4,4>(acc0, x1n,3,1, x1n,3,1, wxx0 + 1*16, s_cg);
    path_fn<2,2,0,4,4>(acc0, x2n,5,1, x2n,5,1, wxx0 + 2*16, s_cg);

    path_fn<0,1,1,4,4>(acc1, x0n,1,1, x1n,3,1, wxx1 + 0*16, s_cg);
    path_fn<1,0,1,4,4>(acc1, x1n,3,1, x0n,1,1, wxx1 + 1*16, s_cg);
    path_fn<1,1,1,4,4>(acc1, x1n,3,1, x1n,3,1, wxx1 + 2*16, s_cg);
    path_fn<1,2,1,4,4>(acc1, x1n,3,1, x2n,5,1, wxx1 + 3*16, s_cg);
    path_fn<2,1,1,4,4>(acc1, x2n,5,1, x1n,3,1, wxx1 + 4*16, s_cg);
    path_fn<2,2,1,4,4>(acc1, x2n,5,1, x2n,5,1, wxx1 + 5*16, s_cg);

    path_fn<0,2,2,4,4>(acc2, x0n,1,1, x2n,5,1, wxx2 + 0*16, s_cg);
    path_fn<1,1,2,4,4>(acc2, x1n,3,1, x1n,3,1, wxx2 + 1*16, s_cg);
    path_fn<1,2,2,4,4>(acc2, x1n,3,1, x2n,5,1, wxx2 + 2*16, s_cg);
    path_fn<2,0,2,4,4>(acc2, x2n,5,1, x0n,1,1, wxx2 + 3*16, s_cg);
    path_fn<2,1,2,4,4>(acc2, x2n,5,1, x1n,3,1, wxx2 + 4*16, s_cg);
    path_fn<2,2,2,4,4>(acc2, x2n,5,1, x2n,5,1, wxx2 + 5*16, s_cg);

    // ---- outputs: out0 [N,8,1] | out1 [N,8,3] | out2 [N,8,5] ----
    out[n * 8 + o] = acc0[0];
    float* o1 = out + 240000 + ((size_t)n * 8 + o) * 3;
    o1[0] = acc1[0]; o1[1] = acc1[1]; o1[2] = acc1[2];
    float* o2 = out + 960000 + ((size_t)n * 8 + o) * 5;
    o2[0] = acc2[0]; o2[1] = acc2[1]; o2[2] = acc2[2]; o2[3] = acc2[3]; o2[4] = acc2[4];
}

// ---------------------------------------------------------------------------
extern "C" void kernel_launch(void* const* d_in, const int* in_sizes, int n_in,
                              void* d_out, int out_size) {
    const float* x0   = (const float*)d_in[0];
    const float* x1   = (const float*)d_in[1];
    const float* x2   = (const float*)d_in[2];
    const float* ev   = (const float*)d_in[3];
    const float* Wxx0 = (const float*)d_in[4];
    const float* Wxx1 = (const float*)d_in[5];
    const float* Wxx2 = (const float*)d_in[6];
    const float* Wyx0 = (const float*)d_in[7];
    const float* Wyx1 = (const float*)d_in[8];
    const float* Wyx2 = (const float*)d_in[9];
    const float* Wyy0 = (const float*)d_in[10];
    const float* Wyy1 = (const float*)d_in[11];
    const float* Wyy2 = (const float*)d_in[12];
    const int* eidx   = (const int*)d_in[13];
    float* out = (float*)d_out;

    zero_kernel<<<(N_NODES * 18 + 255) / 256, 256>>>();
    cg_init_kernel<<<27, 25>>>();
    wt_init_kernel<<<(13440 + 255) / 256, 256>>>(Wyy0, Wyy1, Wyy2,
                                                 Wyx0, Wyx1, Wyx2,
                                                 Wxx0, Wxx1, Wxx2);
    edge_kernel<<<(N_EDGES + 255) / 256, 256>>>(x0, x1, x2, ev, eidx);
    node_kernel<<<(N_NODES + 31) / 32, 256>>>(x0, x1, x2, out);
}

// round 6
// speedup vs baseline: 4.3004x; 1.9358x over previous
#include <cuda_runtime.h>

#define N_NODES 30000
#define N_EDGES 480000

// ---------------------------------------------------------------------------
// Scratch (static device globals — no allocation)
// y layout per node: [l-block][m][ch(8)] -> l=0 @0 (1*8), l=1 @8 (3*8),
// l=2 @32 (5*8). ch = e*4 + c. 72 floats per node.
// ---------------------------------------------------------------------------
__device__ __align__(16) float g_ybuf[N_NODES * 72];

// Compacted CG (selection rule m = (p-l1)+(q-l2)+lo):
// g_cg2[combo*25 + p*5 + q] = C[m(p,q), p, q]  (0 if out of range)
__device__ float g_cg2[27 * 25];

// Transposed weights, o-major then d-major then c:
//   g_wt[toff + o*R + k*(CA*CB) + d*CA + c] = W[(k*CA*CB + c*CB + d)*8 + o]
// Table order: yy0,yy1,yy2,yx0,yx1,yx2,xx0,xx1,xx2
__device__ __align__(16) float g_wt[13440];

// ---------------------------------------------------------------------------
// Kernel 1: zero y accumulator
// ---------------------------------------------------------------------------
__global__ void zero_kernel() {
    int i = blockIdx.x * blockDim.x + threadIdx.x;
    if (i < N_NODES * 18) {
        ((float4*)g_ybuf)[i] = make_float4(0.f, 0.f, 0.f, 0.f);
    }
}

// ---------------------------------------------------------------------------
// Kernel 2: Clebsch-Gordan coefficients (deterministic, tiny)
// ---------------------------------------------------------------------------
__device__ double dfac(int n) {
    double r = 1.0;
    for (int i = 2; i <= n; i++) r *= (double)i;
    return r;
}

__device__ double cg_coeff(int j1, int m1, int j2, int m2, int j, int m) {
    if (m != m1 + m2) return 0.0;
    int dj = j1 - j2; if (dj < 0) dj = -dj;
    if (j < dj || j > j1 + j2) return 0.0;
    double pre = sqrt((2.0 * j + 1.0) * dfac(j + j1 - j2) * dfac(j - j1 + j2) *
                      dfac(j1 + j2 - j) / dfac(j1 + j2 + j + 1));
    pre *= sqrt(dfac(j + m) * dfac(j - m) * dfac(j1 - m1) * dfac(j1 + m1) *
                dfac(j2 - m2) * dfac(j2 + m2));
    double s = 0.0;
    for (int k = 0; k <= j1 + j2 - j; k++) {
        int d0 = k;
        int d1 = j1 + j2 - j - k;
        int d2 = j1 - m1 - k;
        int d3 = j2 + m2 - k;
        int d4 = j - j2 + m1 + k;
        int d5 = j - j1 - m2 + k;
        if (d0 < 0 || d1 < 0 || d2 < 0 || d3 < 0 || d4 < 0 || d5 < 0) continue;
        double den = dfac(d0) * dfac(d1) * dfac(d2) * dfac(d3) * dfac(d4) * dfac(d5);
        s += ((k & 1) ? -1.0 : 1.0) / den;
    }
    return pre * s;
}

__global__ void cg_init_kernel() {
    int combo = blockIdx.x;           // 0..26
    int l1 = combo / 9;
    int l2 = (combo / 3) % 3;
    int lo = combo % 3;
    int t = threadIdx.x;              // 0..24
    int p = t / 5, q = t % 5;
    int m = (p - l1) + (q - l2) + lo; // selection rule
    float val = 0.f;
    if (p <= 2 * l1 && q <= 2 * l2 && m >= 0 && m <= 2 * lo) {
        val = (float)cg_coeff(l1, p - l1, l2, q - l2, lo, m - lo);
    }
    g_cg2[combo * 25 + t] = val;
}

// ---------------------------------------------------------------------------
// Kernel 2b: transpose weight tables into g_wt (one launch, tiny)
// ---------------------------------------------------------------------------
__global__ void wt_init_kernel(const float* __restrict__ w0, const float* __restrict__ w1,
                               const float* __restrict__ w2, const float* __restrict__ w3,
                               const float* __restrict__ w4, const float* __restrict__ w5,
                               const float* __restrict__ w6, const float* __restrict__ w7,
                               const float* __restrict__ w8) {
    int t = blockIdx.x * blockDim.x + threadIdx.x;
    if (t >= 13440) return;
    const int toff[10] = {0, 1536, 4608, 7680, 8448, 9984, 11520, 11904, 12672, 13440};
    const int CAs[9] = {8, 8, 8, 8, 8, 8, 4, 4, 4};
    const int CBs[9] = {8, 8, 8, 4, 4, 4, 4, 4, 4};
    const float* srcs[9] = {w0, w1, w2, w3, w4, w5, w6, w7, w8};
    int T = 0;
    while (t >= toff[T + 1]) T++;
    int u = t - toff[T];
    int R = (toff[T + 1] - toff[T]) / 8;
    int o = u / R;
    int v = u % R;
    int CA = CAs[T], CB = CBs[T], r = CA * CB;
    int k = v / r, w = v % r;
    int d = w / CA, c = w % CA;
    g_wt[t] = srcs[T][(k * r + c * CB + d) * 8 + o];
}

// ---------------------------------------------------------------------------
// Kernel 3: edge gather / outer-product / scatter-add (vector atomics)
// edge_idx is int32 (JAX x64 disabled)
// ---------------------------------------------------------------------------
__device__ __forceinline__ void red4(float* p, float a, float b, float c, float d) {
    asm volatile("red.global.add.v4.f32 [%0], {%1,%2,%3,%4};"
                 :: "l"(p), "f"(a), "f"(b), "f"(c), "f"(d) : "memory");
}

__global__ void edge_kernel(const float* __restrict__ x0,
                            const float* __restrict__ x1,
                            const float* __restrict__ x2,
                            const float* __restrict__ ev,
                            const int* __restrict__ eidx) {
    int e = blockIdx.x * blockDim.x + threadIdx.x;
    if (e >= N_EDGES) return;
    int src = eidx[e];
    int dst = eidx[N_EDGES + e];
    float2 ee = *(const float2*)(ev + 2 * e);
    float* yb = g_ybuf + (size_t)dst * 72;

    {
        float4 a = *(const float4*)(x0 + (size_t)src * 4);
        red4(yb + 0, ee.x * a.x, ee.x * a.y, ee.x * a.z, ee.x * a.w);
        red4(yb + 4, ee.y * a.x, ee.y * a.y, ee.y * a.z, ee.y * a.w);
    }
    {
        float v[12];
        const float4* p = (const float4*)(x1 + (size_t)src * 12);
        ((float4*)v)[0] = p[0];
        ((float4*)v)[1] = p[1];
        ((float4*)v)[2] = p[2];
#pragma unroll
        for (int m = 0; m < 3; m++) {
            red4(yb + 8 + m * 8,
                 ee.x * v[0 * 3 + m], ee.x * v[1 * 3 + m],
                 ee.x * v[2 * 3 + m], ee.x * v[3 * 3 + m]);
            red4(yb + 8 + m * 8 + 4,
                 ee.y * v[0 * 3 + m], ee.y * v[1 * 3 + m],
                 ee.y * v[2 * 3 + m], ee.y * v[3 * 3 + m]);
        }
    }
    {
        float v[20];
        const float4* p = (const float4*)(x2 + (size_t)src * 20);
        ((float4*)v)[0] = p[0];
        ((float4*)v)[1] = p[1];
        ((float4*)v)[2] = p[2];
        ((float4*)v)[3] = p[3];
        ((float4*)v)[4] = p[4];
#pragma unroll
        for (int m = 0; m < 5; m++) {
            red4(yb + 32 + m * 8,
                 ee.x * v[0 * 5 + m], ee.x * v[1 * 5 + m],
                 ee.x * v[2 * 5 + m], ee.x * v[3 * 5 + m]);
            red4(yb + 32 + m * 8 + 4,
                 ee.y * v[0 * 5 + m], ee.y * v[1 * 5 + m],
                 ee.y * v[2 * 5 + m], ee.y * v[3 * 5 + m]);
        }
    }
}

// ---------------------------------------------------------------------------
// Kernel 4: per-(node, o) CG products + SO(3) linear, two warp-halves:
//   half 0: y (x) y paths;  half 1: y (x) x  +  x (x) x paths.
// Halves combine through a padded smem accumulator; half 0 writes out.
// Per path:
//   H[c][q]   = sum_d Wt[d*CA+c] * B[d,q]
//   Pq[q]     = sum_c A[c,p] * H[c][q]
//   acc[m(p,q)] += CG2[p,q] * Pq[q]   (selection rule: one m per (p,q))
// ---------------------------------------------------------------------------
template <int L1, int L2, int LO, int CA, int CB>
__device__ __forceinline__ void path_fn(float* __restrict__ acc,
                                        const float* __restrict__ sA, int Acs, int Aps,
                                        const float* __restrict__ sB, int Bcs, int Bps,
                                        const float* __restrict__ Wt,
                                        const float* __restrict__ sCG2) {
    constexpr int P = 2 * L1 + 1, Q = 2 * L2 + 1, M = 2 * LO + 1;
    const float* Cg = sCG2 + ((L1 * 3 + L2) * 3 + LO) * 25;

    float H[CA][Q];
#pragma unroll
    for (int c = 0; c < CA; c++)
#pragma unroll
        for (int q = 0; q < Q; q++) H[c][q] = 0.f;

#pragma unroll
    for (int d = 0; d < CB; d++) {
        float Bq[Q];
#pragma unroll
        for (int q = 0; q < Q; q++) Bq[q] = sB[d * Bcs + q * Bps];
        float Wc[CA];
        const float4* w4 = (const float4*)(Wt + d * CA);
        ((float4*)Wc)[0] = w4[0];
        if (CA == 8) ((float4*)Wc)[1] = w4[1];
#pragma unroll
        for (int c = 0; c < CA; c++)
#pragma unroll
            for (int q = 0; q < Q; q++) H[c][q] = fmaf(Wc[c], Bq[q], H[c][q]);
    }

#pragma unroll
    for (int p = 0; p < P; p++) {
        float Pq[Q];
#pragma unroll
        for (int q = 0; q < Q; q++) Pq[q] = 0.f;
#pragma unroll
        for (int c = 0; c < CA; c++) {
            float a = sA[c * Acs + p * Aps];
#pragma unroll
            for (int q = 0; q < Q; q++) Pq[q] = fmaf(a, H[c][q], Pq[q]);
        }
#pragma unroll
        for (int q = 0; q < Q; q++) {
            constexpr int base = LO - L1 - L2;  // m = p+q+base
            int mi = p + q + base;
            if (mi >= 0 && mi < M) acc[mi] = fmaf(Cg[p * 5 + q], Pq[q], acc[mi]);
        }
    }
}

#define SY_STRIDE 73
#define SX_STRIDE 37
#define NPB 16   // nodes per block

__global__ __launch_bounds__(256, 2)
void node_kernel(const float* __restrict__ x0, const float* __restrict__ x1,
                 const float* __restrict__ x2, float* __restrict__ out) {
    __shared__ float s_y[NPB * SY_STRIDE];
    __shared__ float s_x[NPB * SX_STRIDE];
    __shared__ float s_cg[27 * 25];
    __shared__ float s_acc[NPB * 8 * 9];   // [(o*16+nl)*9 + k]

    int tid = threadIdx.x;
    int nblk = blockIdx.x * NPB;

    // stage y: 16 nodes x 72 floats (padded stride)
    for (int i = tid; i < NPB * 72; i += 256) {
        int nl = i / 72, j = i % 72;
        s_y[nl * SY_STRIDE + j] = g_ybuf[(size_t)(nblk + nl) * 72 + j];
    }
    // stage x: 16 nodes x 36 floats (x0:4, x1:12, x2:20), padded stride
    for (int i = tid; i < NPB * 36; i += 256) {
        int nl = i / 36, j = i % 36;
        int gn = nblk + nl;
        float v;
        if (j < 4)       v = x0[(size_t)gn * 4 + j];
        else if (j < 16) v = x1[(size_t)gn * 12 + (j - 4)];
        else             v = x2[(size_t)gn * 20 + (j - 16)];
        s_x[nl * SX_STRIDE + j] = v;
    }
    // stage compact CG table
    for (int i = tid; i < 27 * 25; i += 256) s_cg[i] = g_cg2[i];
    __syncthreads();

    // thread mapping: half = tid>>7; within half: warp_in_half (0..3), lane.
    // nl = lane&15 (node), o = (lane>>4) + 2*warp_in_half  (W 2-way broadcast)
    int half = tid >> 7;
    int ht = tid & 127;
    int lane = ht & 31;
    int nl = lane & 15;
    int o = (lane >> 4) + ((ht >> 5) << 1);
    int n = nblk + nl;   // always < N_NODES (30000 = 1875*16)

    const float* sy = s_y + nl * SY_STRIDE;
    const float* sx = s_x + nl * SX_STRIDE;
    const float* y0p = sy;        // (c,q): c*1 + q*8
    const float* y1p = sy + 8;
    const float* y2p = sy + 32;
    const float* x0n = sx;        // (c,q): c*1 + q*1
    const float* x1n = sx + 4;    // (c,q): c*3 + q
    const float* x2n = sx + 16;   // (c,q): c*5 + q

    float acc0[1] = {0.f};
    float acc1[3] = {0.f, 0.f, 0.f};
    float acc2[5] = {0.f, 0.f, 0.f, 0.f, 0.f};

    if (half == 0) {
        // ---- y x y (CA=8, CB=8) ----
        const float* wyy0 = g_wt + 0    + o * 192;
        const float* wyy1 = g_wt + 1536 + o * 384;
        const float* wyy2 = g_wt + 4608 + o * 384;

        path_fn<0,0,0,8,8>(acc0, y0p,1,8, y0p,1,8, wyy0 + 0*64, s_cg);
        path_fn<1,1,0,8,8>(acc0, y1p,1,8, y1p,1,8, wyy0 + 1*64, s_cg);
        path_fn<2,2,0,8,8>(acc0, y2p,1,8, y2p,1,8, wyy0 + 2*64, s_cg);

        path_fn<0,1,1,8,8>(acc1, y0p,1,8, y1p,1,8, wyy1 + 0*64, s_cg);
        path_fn<1,0,1,8,8>(acc1, y1p,1,8, y0p,1,8, wyy1 + 1*64, s_cg);
        path_fn<1,1,1,8,8>(acc1, y1p,1,8, y1p,1,8, wyy1 + 2*64, s_cg);
        path_fn<1,2,1,8,8>(acc1, y1p,1,8, y2p,1,8, wyy1 + 3*64, s_cg);
        path_fn<2,1,1,8,8>(acc1, y2p,1,8, y1p,1,8, wyy1 + 4*64, s_cg);
        path_fn<2,2,1,8,8>(acc1, y2p,1,8, y2p,1,8, wyy1 + 5*64, s_cg);

        path_fn<0,2,2,8,8>(acc2, y0p,1,8, y2p,1,8, wyy2 + 0*64, s_cg);
        path_fn<1,1,2,8,8>(acc2, y1p,1,8, y1p,1,8, wyy2 + 1*64, s_cg);
        path_fn<1,2,2,8,8>(acc2, y1p,1,8, y2p,1,8, wyy2 + 2*64, s_cg);
        path_fn<2,0,2,8,8>(acc2, y2p,1,8, y0p,1,8, wyy2 + 3*64, s_cg);
        path_fn<2,1,2,8,8>(acc2, y2p,1,8, y1p,1,8, wyy2 + 4*64, s_cg);
        path_fn<2,2,2,8,8>(acc2, y2p,1,8, y2p,1,8, wyy2 + 5*64, s_cg);
    } else {
        // ---- y x x (CA=8, CB=4) ----
        const float* wyx0 = g_wt + 7680  + o * 96;
        const float* wyx1 = g_wt + 8448  + o * 192;
        const float* wyx2 = g_wt + 9984  + o * 192;
        const float* wxx0 = g_wt + 11520 + o * 48;
        const float* wxx1 = g_wt + 11904 + o * 96;
        const float* wxx2 = g_wt + 12672 + o * 96;

        path_fn<0,0,0,8,4>(acc0, y0p,1,8, x0n,1,1, wyx0 + 0*32, s_cg);
        path_fn<1,1,0,8,4>(acc0, y1p,1,8, x1n,3,1, wyx0 + 1*32, s_cg);
        path_fn<2,2,0,8,4>(acc0, y2p,1,8, x2n,5,1, wyx0 + 2*32, s_cg);

        path_fn<0,1,1,8,4>(acc1, y0p,1,8, x1n,3,1, wyx1 + 0*32, s_cg);
        path_fn<1,0,1,8,4>(acc1, y1p,1,8, x0n,1,1, wyx1 + 1*32, s_cg);
        path_fn<1,1,1,8,4>(acc1, y1p,1,8, x1n,3,1, wyx1 + 2*32, s_cg);
        path_fn<1,2,1,8,4>(acc1, y1p,1,8, x2n,5,1, wyx1 + 3*32, s_cg);
        path_fn<2,1,1,8,4>(acc1, y2p,1,8, x1n,3,1, wyx1 + 4*32, s_cg);
        path_fn<2,2,1,8,4>(acc1, y2p,1,8, x2n,5,1, wyx1 + 5*32, s_cg);

        path_fn<0,2,2,8,4>(acc2, y0p,1,8, x2n,5,1, wyx2 + 0*32, s_cg);
        path_fn<1,1,2,8,4>(acc2, y1p,1,8, x1n,3,1, wyx2 + 1*32, s_cg);
        path_fn<1,2,2,8,4>(acc2, y1p,1,8, x2n,5,1, wyx2 + 2*32, s_cg);
        path_fn<2,0,2,8,4>(acc2, y2p,1,8, x0n,1,1, wyx2 + 3*32, s_cg);
        path_fn<2,1,2,8,4>(acc2, y2p,1,8, x1n,3,1, wyx2 + 4*32, s_cg);
        path_fn<2,2,2,8,4>(acc2, y2p,1,8, x2n,5,1, wyx2 + 5*32, s_cg);

        // ---- x x x (CA=4, CB=4) ----
        path_fn<0,0,0,4,4>(acc0, x0n,1,1, x0n,1,1, wxx0 + 0*16, s_cg);
        path_fn<1,1,0,4,4>(acc0, x1n,3,1, x1n,3,1, wxx0 + 1*16, s_cg);
        path_fn<2,2,0,4,4>(acc0, x2n,5,1, x2n,5,1, wxx0 + 2*16, s_cg);

        path_fn<0,1,1,4,4>(acc1, x0n,1,1, x1n,3,1, wxx1 + 0*16, s_cg);
        path_fn<1,0,1,4,4>(acc1, x1n,3,1, x0n,1,1, wxx1 + 1*16, s_cg);
        path_fn<1,1,1,4,4>(acc1, x1n,3,1, x1n,3,1, wxx1 + 2*16, s_cg);
        path_fn<1,2,1,4,4>(acc1, x1n,3,1, x2n,5,1, wxx1 + 3*16, s_cg);
        path_fn<2,1,1,4,4>(acc1, x2n,5,1, x1n,3,1, wxx1 + 4*16, s_cg);
        path_fn<2,2,1,4,4>(acc1, x2n,5,1, x2n,5,1, wxx1 + 5*16, s_cg);

        path_fn<0,2,2,4,4>(acc2, x0n,1,1, x2n,5,1, wxx2 + 0*16, s_cg);
        path_fn<1,1,2,4,4>(acc2, x1n,3,1, x1n,3,1, wxx2 + 1*16, s_cg);
        path_fn<1,2,2,4,4>(acc2, x1n,3,1, x2n,5,1, wxx2 + 2*16, s_cg);
        path_fn<2,0,2,4,4>(acc2, x2n,5,1, x0n,1,1, wxx2 + 3*16, s_cg);
        path_fn<2,1,2,4,4>(acc2, x2n,5,1, x1n,3,1, wxx2 + 4*16, s_cg);
        path_fn<2,2,2,4,4>(acc2, x2n,5,1, x2n,5,1, wxx2 + 5*16, s_cg);
    }

    // ---- combine halves via smem (padded: stride 9 per (o,nl) slot) ----
    float* sa = s_acc + (o * NPB + nl) * 9;
    if (half == 1) {
        sa[0] = acc0[0];
        sa[1] = acc1[0]; sa[2] = acc1[1]; sa[3] = acc1[2];
        sa[4] = acc2[0]; sa[5] = acc2[1]; sa[6] = acc2[2];
        sa[7] = acc2[3]; sa[8] = acc2[4];
    }
    __syncthreads();
    if (half == 0) {
        out[n * 8 + o] = acc0[0] + sa[0];
        float* o1 = out + 240000 + ((size_t)n * 8 + o) * 3;
        o1[0] = acc1[0] + sa[1]; o1[1] = acc1[1] + sa[2]; o1[2] = acc1[2] + sa[3];
        float* o2 = out + 960000 + ((size_t)n * 8 + o) * 5;
        o2[0] = acc2[0] + sa[4]; o2[1] = acc2[1] + sa[5]; o2[2] = acc2[2] + sa[6];
        o2[3] = acc2[3] + sa[7]; o2[4] = acc2[4] + sa[8];
    }
}

// ---------------------------------------------------------------------------
extern "C" void kernel_launch(void* const* d_in, const int* in_sizes, int n_in,
                              void* d_out, int out_size) {
    const float* x0   = (const float*)d_in[0];
    const float* x1   = (const float*)d_in[1];
    const float* x2   = (const float*)d_in[2];
    const float* ev   = (const float*)d_in[3];
    const float* Wxx0 = (const float*)d_in[4];
    const float* Wxx1 = (const float*)d_in[5];
    const float* Wxx2 = (const float*)d_in[6];
    const float* Wyx0 = (const float*)d_in[7];
    const float* Wyx1 = (const float*)d_in[8];
    const float* Wyx2 = (const float*)d_in[9];
    const float* Wyy0 = (const float*)d_in[10];
    const float* Wyy1 = (const float*)d_in[11];
    const float* Wyy2 = (const float*)d_in[12];
    const int* eidx   = (const int*)d_in[13];
    float* out = (float*)d_out;

    zero_kernel<<<(N_NODES * 18 + 255) / 256, 256>>>();
    cg_init_kernel<<<27, 25>>>();
    wt_init_kernel<<<(13440 + 255) / 256, 256>>>(Wyy0, Wyy1, Wyy2,
                                                 Wyx0, Wyx1, Wyx2,
                                                 Wxx0, Wxx1, Wxx2);
    edge_kernel<<<(N_EDGES + 255) / 256, 256>>>(x0, x1, x2, ev, eidx);
    node_kernel<<<N_NODES / NPB, 256>>>(x0, x1, x2, out);
}

// round 7
// speedup vs baseline: 4.6805x; 1.0884x over previous
#include <cuda_runtime.h>

#define N_NODES 30000
#define N_EDGES 480000

// ---------------------------------------------------------------------------
// Scratch (static device globals — no allocation)
// y layout per node: [l-block][m][ch(8)] -> l=0 @0 (1*8), l=1 @8 (3*8),
// l=2 @32 (5*8). ch = e*4 + c. 72 floats per node.
// ---------------------------------------------------------------------------
__device__ __align__(16) float g_ybuf[N_NODES * 72];

// Compacted CG (selection rule m = (p-l1)+(q-l2)+lo):
// g_cg2[combo*25 + p*5 + q] = C[m(p,q), p, q]  (0 if out of range)
__device__ float g_cg2[27 * 25];

// Fused + transposed weights. Families: yy (CA=CB=8, 11 fused paths),
// yx (CA=8, CB=4, 15 paths), xx (CA=CB=4, 11 fused paths).
// Layout: family base + o*R + path*(CA*CB) + d*CA + c.
//   yy: base 0,    R=704 (11*64), size 5632
//   yx: base 5632, R=480 (15*32), size 3840
//   xx: base 9472, R=176 (11*16), size 1408
__device__ __align__(16) float g_wt[10880];

// ---------------------------------------------------------------------------
// Kernel 1: zero y accumulator
// ---------------------------------------------------------------------------
__global__ void zero_kernel() {
    int i = blockIdx.x * blockDim.x + threadIdx.x;
    if (i < N_NODES * 18) {
        ((float4*)g_ybuf)[i] = make_float4(0.f, 0.f, 0.f, 0.f);
    }
}

// ---------------------------------------------------------------------------
// Kernel 2: Clebsch-Gordan coefficients (deterministic, tiny)
// ---------------------------------------------------------------------------
__device__ double dfac(int n) {
    double r = 1.0;
    for (int i = 2; i <= n; i++) r *= (double)i;
    return r;
}

__device__ double cg_coeff(int j1, int m1, int j2, int m2, int j, int m) {
    if (m != m1 + m2) return 0.0;
    int dj = j1 - j2; if (dj < 0) dj = -dj;
    if (j < dj || j > j1 + j2) return 0.0;
    double pre = sqrt((2.0 * j + 1.0) * dfac(j + j1 - j2) * dfac(j - j1 + j2) *
                      dfac(j1 + j2 - j) / dfac(j1 + j2 + j + 1));
    pre *= sqrt(dfac(j + m) * dfac(j - m) * dfac(j1 - m1) * dfac(j1 + m1) *
                dfac(j2 - m2) * dfac(j2 + m2));
    double s = 0.0;
    for (int k = 0; k <= j1 + j2 - j; k++) {
        int d0 = k;
        int d1 = j1 + j2 - j - k;
        int d2 = j1 - m1 - k;
        int d3 = j2 + m2 - k;
        int d4 = j - j2 + m1 + k;
        int d5 = j - j1 - m2 + k;
        if (d0 < 0 || d1 < 0 || d2 < 0 || d3 < 0 || d4 < 0 || d5 < 0) continue;
        double den = dfac(d0) * dfac(d1) * dfac(d2) * dfac(d3) * dfac(d4) * dfac(d5);
        s += ((k & 1) ? -1.0 : 1.0) / den;
    }
    return pre * s;
}

__global__ void cg_init_kernel() {
    int combo = blockIdx.x;           // 0..26
    int l1 = combo / 9;
    int l2 = (combo / 3) % 3;
    int lo = combo % 3;
    int t = threadIdx.x;              // 0..24
    int p = t / 5, q = t % 5;
    int m = (p - l1) + (q - l2) + lo; // selection rule
    float val = 0.f;
    if (p <= 2 * l1 && q <= 2 * l2 && m >= 0 && m <= 2 * lo) {
        val = (float)cg_coeff(l1, p - l1, l2, q - l2, lo, m - lo);
    }
    g_cg2[combo * 25 + t] = val;
}

// ---------------------------------------------------------------------------
// Kernel 2b: build fused+transposed weight table.
// Fused path list (yy/xx; same-operand CG symmetry, s = (-1)^(l1+l2-lo)):
//   idx: (l1,l2,lo)  src family k   pair k  sign
//   0:(0,0,0)F0k0  1:(1,1,0)F0k1  2:(2,2,0)F0k2
//   3:(0,1,1)F1k0+F1k1^T(+1) 4:(1,1,1)F1k2 5:(1,2,1)F1k3+F1k4^T(+1) 6:(2,2,1)F1k5
//   7:(0,2,2)F2k0+F2k3^T(+1) 8:(1,1,2)F2k1 9:(1,2,2)F2k2+F2k4^T(-1) 10:(2,2,2)F2k5
// ---------------------------------------------------------------------------
__global__ void wt_init_kernel(const float* __restrict__ wyy0, const float* __restrict__ wyy1,
                               const float* __restrict__ wyy2, const float* __restrict__ wyx0,
                               const float* __restrict__ wyx1, const float* __restrict__ wyx2,
                               const float* __restrict__ wxx0, const float* __restrict__ wxx1,
                               const float* __restrict__ wxx2) {
    int t = blockIdx.x * blockDim.x + threadIdx.x;
    if (t >= 10880) return;

    const int  loF[11]   = {0, 0, 0, 1, 1, 1, 1, 2, 2, 2, 2};
    const int  srcK[11]  = {0, 1, 2, 0, 2, 3, 5, 0, 1, 2, 5};
    const int  pairK[11] = {-1, -1, -1, 1, -1, 4, -1, 3, -1, 4, -1};
    const float sgn[11]  = {0.f, 0.f, 0.f, 1.f, 0.f, 1.f, 0.f, 1.f, 0.f, -1.f, 0.f};

    float val;
    if (t < 5632) {                       // yy: CA=CB=8
        int u = t, R = 704, r = 64;
        int o = u / R, v = u % R;
        int pk = v / r, w = v % r, d = w / 8, c = w % 8;
        const float* S[3] = {wyy0, wyy1, wyy2};
        const float* src = S[loF[pk]];
        val = src[(srcK[pk] * r + c * 8 + d) * 8 + o];
        if (pairK[pk] >= 0)
            val += sgn[pk] * src[(pairK[pk] * r + d * 8 + c) * 8 + o];
    } else if (t < 9472) {                // yx: CA=8, CB=4, unfused 15 paths
        int u = t - 5632, R = 480, r = 32;
        int o = u / R, v = u % R;
        int pk = v / r, w = v % r, d = w / 8, c = w % 8;
        int lo = (pk < 3) ? 0 : (pk < 9 ? 1 : 2);
        int k = pk - (lo == 0 ? 0 : (lo == 1 ? 3 : 9));
        const float* S[3] = {wyx0, wyx1, wyx2};
        val = S[lo][(k * r + c * 4 + d) * 8 + o];
    } else {                              // xx: CA=CB=4, fused
        int u = t - 9472, R = 176, r = 16;
        int o = u / R, v = u % R;
        int pk = v / r, w = v % r, d = w / 4, c = w % 4;
        const float* S[3] = {wxx0, wxx1, wxx2};
        const float* src = S[loF[pk]];
        val = src[(srcK[pk] * r + c * 4 + d) * 8 + o];
        if (pairK[pk] >= 0)
            val += sgn[pk] * src[(pairK[pk] * r + d * 4 + c) * 8 + o];
    }
    g_wt[t] = val;
}

// ---------------------------------------------------------------------------
// Kernel 3: edge gather / outer-product / scatter-add (vector atomics)
// edge_idx is int32 (JAX x64 disabled)
// ---------------------------------------------------------------------------
__device__ __forceinline__ void red4(float* p, float a, float b, float c, float d) {
    asm volatile("red.global.add.v4.f32 [%0], {%1,%2,%3,%4};"
                 :: "l"(p), "f"(a), "f"(b), "f"(c), "f"(d) : "memory");
}

__global__ void edge_kernel(const float* __restrict__ x0,
                            const float* __restrict__ x1,
                            const float* __restrict__ x2,
                            const float* __restrict__ ev,
                            const int* __restrict__ eidx) {
    int e = blockIdx.x * blockDim.x + threadIdx.x;
    if (e >= N_EDGES) return;
    int src = eidx[e];
    int dst = eidx[N_EDGES + e];
    float2 ee = *(const float2*)(ev + 2 * e);
    float* yb = g_ybuf + (size_t)dst * 72;

    {
        float4 a = *(const float4*)(x0 + (size_t)src * 4);
        red4(yb + 0, ee.x * a.x, ee.x * a.y, ee.x * a.z, ee.x * a.w);
        red4(yb + 4, ee.y * a.x, ee.y * a.y, ee.y * a.z, ee.y * a.w);
    }
    {
        float v[12];
        const float4* p = (const float4*)(x1 + (size_t)src * 12);
        ((float4*)v)[0] = p[0];
        ((float4*)v)[1] = p[1];
        ((float4*)v)[2] = p[2];
#pragma unroll
        for (int m = 0; m < 3; m++) {
            red4(yb + 8 + m * 8,
                 ee.x * v[0 * 3 + m], ee.x * v[1 * 3 + m],
                 ee.x * v[2 * 3 + m], ee.x * v[3 * 3 + m]);
            red4(yb + 8 + m * 8 + 4,
                 ee.y * v[0 * 3 + m], ee.y * v[1 * 3 + m],
                 ee.y * v[2 * 3 + m], ee.y * v[3 * 3 + m]);
        }
    }
    {
        float v[20];
        const float4* p = (const float4*)(x2 + (size_t)src * 20);
        ((float4*)v)[0] = p[0];
        ((float4*)v)[1] = p[1];
        ((float4*)v)[2] = p[2];
        ((float4*)v)[3] = p[3];
        ((float4*)v)[4] = p[4];
#pragma unroll
        for (int m = 0; m < 5; m++) {
            red4(yb + 32 + m * 8,
                 ee.x * v[0 * 5 + m], ee.x * v[1 * 5 + m],
                 ee.x * v[2 * 5 + m], ee.x * v[3 * 5 + m]);
            red4(yb + 32 + m * 8 + 4,
                 ee.y * v[0 * 5 + m], ee.y * v[1 * 5 + m],
                 ee.y * v[2 * 5 + m], ee.y * v[3 * 5 + m]);
        }
    }
}

// ---------------------------------------------------------------------------
// Kernel 4: node compute. Two warp-halves per block:
//   half 0: fused y(x)y paths (all-register operands)
//   half 1: y(x)x (A in regs, B in smem) + fused x(x)x (smem)
// ---------------------------------------------------------------------------

// A, B both register arrays ([c*P+p] / [d*Q+q], 8 channels each)
template <int L1, int L2, int LO>
__device__ __forceinline__ void path_rr(float* __restrict__ acc,
                                        const float (&A)[8 * (2 * L1 + 1)],
                                        const float (&B)[8 * (2 * L2 + 1)],
                                        const float* __restrict__ Wt,
                                        const float* __restrict__ sCG) {
    constexpr int P = 2 * L1 + 1, Q = 2 * L2 + 1, M = 2 * LO + 1;
    const float* Cg = sCG + ((L1 * 3 + L2) * 3 + LO) * 25;
    float H[8][Q];
#pragma unroll
    for (int c = 0; c < 8; c++)
#pragma unroll
        for (int q = 0; q < Q; q++) H[c][q] = 0.f;
#pragma unroll
    for (int d = 0; d < 8; d++) {
        float Wc[8];
        ((float4*)Wc)[0] = ((const float4*)(Wt + d * 8))[0];
        ((float4*)Wc)[1] = ((const float4*)(Wt + d * 8))[1];
#pragma unroll
        for (int c = 0; c < 8; c++)
#pragma unroll
            for (int q = 0; q < Q; q++) H[c][q] = fmaf(Wc[c], B[d * Q + q], H[c][q]);
    }
#pragma unroll
    for (int p = 0; p < P; p++) {
        float Pq[Q];
#pragma unroll
        for (int q = 0; q < Q; q++) Pq[q] = 0.f;
#pragma unroll
        for (int c = 0; c < 8; c++) {
            float a = A[c * P + p];
#pragma unroll
            for (int q = 0; q < Q; q++) Pq[q] = fmaf(a, H[c][q], Pq[q]);
        }
#pragma unroll
        for (int q = 0; q < Q; q++) {
            constexpr int base = LO - L1 - L2;
            int mi = p + q + base;
            if (mi >= 0 && mi < M) acc[mi] = fmaf(Cg[p * 5 + q], Pq[q], acc[mi]);
        }
    }
}

// A register array (8 ch), B smem (4 ch, [d*Q+q])
template <int L1, int L2, int LO>
__device__ __forceinline__ void path_rs(float* __restrict__ acc,
                                        const float (&A)[8 * (2 * L1 + 1)],
                                        const float* __restrict__ sB,
                                        const float* __restrict__ Wt,
                                        const float* __restrict__ sCG) {
    constexpr int P = 2 * L1 + 1, Q = 2 * L2 + 1, M = 2 * LO + 1;
    const float* Cg = sCG + ((L1 * 3 + L2) * 3 + LO) * 25;
    float H[8][Q];
#pragma unroll
    for (int c = 0; c < 8; c++)
#pragma unroll
        for (int q = 0; q < Q; q++) H[c][q] = 0.f;
#pragma unroll
    for (int d = 0; d < 4; d++) {
        float Bq[Q];
#pragma unroll
        for (int q = 0; q < Q; q++) Bq[q] = sB[d * Q + q];
        float Wc[8];
        ((float4*)Wc)[0] = ((const float4*)(Wt + d * 8))[0];
        ((float4*)Wc)[1] = ((const float4*)(Wt + d * 8))[1];
#pragma unroll
        for (int c = 0; c < 8; c++)
#pragma unroll
            for (int q = 0; q < Q; q++) H[c][q] = fmaf(Wc[c], Bq[q], H[c][q]);
    }
#pragma unroll
    for (int p = 0; p < P; p++) {
        float Pq[Q];
#pragma unroll
        for (int q = 0; q < Q; q++) Pq[q] = 0.f;
#pragma unroll
        for (int c = 0; c < 8; c++) {
            float a = A[c * P + p];
#pragma unroll
            for (int q = 0; q < Q; q++) Pq[q] = fmaf(a, H[c][q], Pq[q]);
        }
#pragma unroll
        for (int q = 0; q < Q; q++) {
            constexpr int base = LO - L1 - L2;
            int mi = p + q + base;
            if (mi >= 0 && mi < M) acc[mi] = fmaf(Cg[p * 5 + q], Pq[q], acc[mi]);
        }
    }
}

// A, B both smem (4 ch each, [c*P+p] / [d*Q+q])
template <int L1, int L2, int LO>
__device__ __forceinline__ void path_ss(float* __restrict__ acc,
                                        const float* __restrict__ sA,
                                        const float* __restrict__ sB,
                                        const float* __restrict__ Wt,
                                        const float* __restrict__ sCG) {
    constexpr int P = 2 * L1 + 1, Q = 2 * L2 + 1, M = 2 * LO + 1;
    const float* Cg = sCG + ((L1 * 3 + L2) * 3 + LO) * 25;
    float H[4][Q];
#pragma unroll
    for (int c = 0; c < 4; c++)
#pragma unroll
        for (int q = 0; q < Q; q++) H[c][q] = 0.f;
#pragma unroll
    for (int d = 0; d < 4; d++) {
        float Bq[Q];
#pragma unroll
        for (int q = 0; q < Q; q++) Bq[q] = sB[d * Q + q];
        float Wc[4];
        ((float4*)Wc)[0] = ((const float4*)(Wt + d * 4))[0];
#pragma unroll
        for (int c = 0; c < 4; c++)
#pragma unroll
            for (int q = 0; q < Q; q++) H[c][q] = fmaf(Wc[c], Bq[q], H[c][q]);
    }
#pragma unroll
    for (int p = 0; p < P; p++) {
        float Pq[Q];
#pragma unroll
        for (int q = 0; q < Q; q++) Pq[q] = 0.f;
#pragma unroll
        for (int c = 0; c < 4; c++) {
            float a = sA[c * P + p];
#pragma unroll
            for (int q = 0; q < Q; q++) Pq[q] = fmaf(a, H[c][q], Pq[q]);
        }
#pragma unroll
        for (int q = 0; q < Q; q++) {
            constexpr int base = LO - L1 - L2;
            int mi = p + q + base;
            if (mi >= 0 && mi < M) acc[mi] = fmaf(Cg[p * 5 + q], Pq[q], acc[mi]);
        }
    }
}

#define SY_STRIDE 73
#define SX_STRIDE 37
#define NPB 8   // nodes per block

__global__ __launch_bounds__(128, 3)
void node_kernel(const float* __restrict__ x0, const float* __restrict__ x1,
                 const float* __restrict__ x2, float* __restrict__ out) {
    __shared__ float s_y[NPB * SY_STRIDE];
    __shared__ float s_x[NPB * SX_STRIDE];
    __shared__ float s_cg[27 * 25];
    __shared__ float s_acc[NPB * 8 * 9];   // [(o*NPB+nl)*9 + k]

    int tid = threadIdx.x;
    int nblk = blockIdx.x * NPB;

    // stage y: 8 nodes x 72 floats (padded stride)
    for (int i = tid; i < NPB * 72; i += 128) {
        int nl = i / 72, j = i % 72;
        s_y[nl * SY_STRIDE + j] = g_ybuf[(size_t)(nblk + nl) * 72 + j];
    }
    // stage x: 8 nodes x 36 floats (x0:4, x1:12, x2:20)
    for (int i = tid; i < NPB * 36; i += 128) {
        int nl = i / 36, j = i % 36;
        int gn = nblk + nl;
        float v;
        if (j < 4)       v = x0[(size_t)gn * 4 + j];
        else if (j < 16) v = x1[(size_t)gn * 12 + (j - 4)];
        else             v = x2[(size_t)gn * 20 + (j - 16)];
        s_x[nl * SX_STRIDE + j] = v;
    }
    // stage compact CG
    for (int i = tid; i < 27 * 25; i += 128) s_cg[i] = g_cg2[i];
    __syncthreads();

    // mapping: half = tid>>6 (warps 0,1 vs 2,3); within half: nl = ht&7, o = ht>>3
    int half = tid >> 6;
    int ht = tid & 63;
    int nl = ht & 7;
    int o = ht >> 3;
    int n = nblk + nl;   // exact: 30000 = 3750*8

    const float* sy = s_y + nl * SY_STRIDE;
    const float* sx = s_x + nl * SX_STRIDE;

    // y into registers: Yl[c*(2l+1)+q]; y smem layout: sy[off_l + q*8 + c]
    float Y0[8], Y1[24], Y2[40];
#pragma unroll
    for (int c = 0; c < 8; c++) Y0[c] = sy[c];
#pragma unroll
    for (int c = 0; c < 8; c++)
#pragma unroll
        for (int q = 0; q < 3; q++) Y1[c * 3 + q] = sy[8 + q * 8 + c];
#pragma unroll
    for (int c = 0; c < 8; c++)
#pragma unroll
        for (int q = 0; q < 5; q++) Y2[c * 5 + q] = sy[32 + q * 8 + c];

    float acc0[1] = {0.f};
    float acc1[3] = {0.f, 0.f, 0.f};
    float acc2[5] = {0.f, 0.f, 0.f, 0.f, 0.f};

    if (half == 0) {
        // ---- fused y x y (11 paths) ----
        const float* wyy = g_wt + o * 704;
        path_rr<0,0,0>(acc0, Y0, Y0, wyy + 0,   s_cg);
        path_rr<1,1,0>(acc0, Y1, Y1, wyy + 64,  s_cg);
        path_rr<2,2,0>(acc0, Y2, Y2, wyy + 128, s_cg);
        path_rr<0,1,1>(acc1, Y0, Y1, wyy + 192, s_cg);
        path_rr<1,1,1>(acc1, Y1, Y1, wyy + 256, s_cg);
        path_rr<1,2,1>(acc1, Y1, Y2, wyy + 320, s_cg);
        path_rr<2,2,1>(acc1, Y2, Y2, wyy + 384, s_cg);
        path_rr<0,2,2>(acc2, Y0, Y2, wyy + 448, s_cg);
        path_rr<1,1,2>(acc2, Y1, Y1, wyy + 512, s_cg);
        path_rr<1,2,2>(acc2, Y1, Y2, wyy + 576, s_cg);
        path_rr<2,2,2>(acc2, Y2, Y2, wyy + 640, s_cg);
    } else {
        const float* x0n = sx;        // [d*1+q]
        const float* x1n = sx + 4;    // [d*3+q]
        const float* x2n = sx + 16;   // [d*5+q]

        // ---- y x x (15 paths, A = Y regs, B = x smem) ----
        const float* wyx = g_wt + 5632 + o * 480;
        path_rs<0,0,0>(acc0, Y0, x0n, wyx + 0,   s_cg);
        path_rs<1,1,0>(acc0, Y1, x1n, wyx + 32,  s_cg);
        path_rs<2,2,0>(acc0, Y2, x2n, wyx + 64,  s_cg);
        path_rs<0,1,1>(acc1, Y0, x1n, wyx + 96,  s_cg);
        path_rs<1,0,1>(acc1, Y1, x0n, wyx + 128, s_cg);
        path_rs<1,1,1>(acc1, Y1, x1n, wyx + 160, s_cg);
        path_rs<1,2,1>(acc1, Y1, x2n, wyx + 192, s_cg);
        path_rs<2,1,1>(acc1, Y2, x1n, wyx + 224, s_cg);
        path_rs<2,2,1>(acc1, Y2, x2n, wyx + 256, s_cg);
        path_rs<0,2,2>(acc2, Y0, x2n, wyx + 288, s_cg);
        path_rs<1,1,2>(acc2, Y1, x1n, wyx + 320, s_cg);
        path_rs<1,2,2>(acc2, Y1, x2n, wyx + 352, s_cg);
        path_rs<2,0,2>(acc2, Y2, x0n, wyx + 384, s_cg);
        path_rs<2,1,2>(acc2, Y2, x1n, wyx + 416, s_cg);
        path_rs<2,2,2>(acc2, Y2, x2n, wyx + 448, s_cg);

        // ---- fused x x x (11 paths, smem) ----
        const float* wxx = g_wt + 9472 + o * 176;
        path_ss<0,0,0>(acc0, x0n, x0n, wxx + 0,   s_cg);
        path_ss<1,1,0>(acc0, x1n, x1n, wxx + 16,  s_cg);
        path_ss<2,2,0>(acc0, x2n, x2n, wxx + 32,  s_cg);
        path_ss<0,1,1>(acc1, x0n, x1n, wxx + 48,  s_cg);
        path_ss<1,1,1>(acc1, x1n, x1n, wxx + 64,  s_cg);
        path_ss<1,2,1>(acc1, x1n, x2n, wxx + 80,  s_cg);
        path_ss<2,2,1>(acc1, x2n, x2n, wxx + 96,  s_cg);
        path_ss<0,2,2>(acc2, x0n, x2n, wxx + 112, s_cg);
        path_ss<1,1,2>(acc2, x1n, x1n, wxx + 128, s_cg);
        path_ss<1,2,2>(acc2, x1n, x2n, wxx + 144, s_cg);
        path_ss<2,2,2>(acc2, x2n, x2n, wxx + 160, s_cg);
    }

    // ---- combine halves via smem (stride 9, conflict-free) ----
    float* sa = s_acc + (o * NPB + nl) * 9;
    if (half == 1) {
        sa[0] = acc0[0];
        sa[1] = acc1[0]; sa[2] = acc1[1]; sa[3] = acc1[2];
        sa[4] = acc2[0]; sa[5] = acc2[1]; sa[6] = acc2[2];
        sa[7] = acc2[3]; sa[8] = acc2[4];
    }
    __syncthreads();
    if (half == 0) {
        out[n * 8 + o] = acc0[0] + sa[0];
        float* o1 = out + 240000 + ((size_t)n * 8 + o) * 3;
        o1[0] = acc1[0] + sa[1]; o1[1] = acc1[1] + sa[2]; o1[2] = acc1[2] + sa[3];
        float* o2 = out + 960000 + ((size_t)n * 8 + o) * 5;
        o2[0] = acc2[0] + sa[4]; o2[1] = acc2[1] + sa[5]; o2[2] = acc2[2] + sa[6];
        o2[3] = acc2[3] + sa[7]; o2[4] = acc2[4] + sa[8];
    }
}

// ---------------------------------------------------------------------------
extern "C" void kernel_launch(void* const* d_in, const int* in_sizes, int n_in,
                              void* d_out, int out_size) {
    const float* x0   = (const float*)d_in[0];
    const float* x1   = (const float*)d_in[1];
    const float* x2   = (const float*)d_in[2];
    const float* ev   = (const float*)d_in[3];
    const float* Wxx0 = (const float*)d_in[4];
    const float* Wxx1 = (const float*)d_in[5];
    const float* Wxx2 = (const float*)d_in[6];
    const float* Wyx0 = (const float*)d_in[7];
    const float* Wyx1 = (const float*)d_in[8];
    const float* Wyx2 = (const float*)d_in[9];
    const float* Wyy0 = (const float*)d_in[10];
    const float* Wyy1 = (const float*)d_in[11];
    const float* Wyy2 = (const float*)d_in[12];
    const int* eidx   = (const int*)d_in[13];
    float* out = (float*)d_out;

    zero_kernel<<<(N_NODES * 18 + 255) / 256, 256>>>();
    cg_init_kernel<<<27, 25>>>();
    wt_init_kernel<<<(10880 + 255) / 256, 256>>>(Wyy0, Wyy1, Wyy2,
                                                 Wyx0, Wyx1, Wyx2,
                                                 Wxx0, Wxx1, Wxx2);
    edge_kernel<<<(N_EDGES + 255) / 256, 256>>>(x0, x1, x2, ev, eidx);
    node_kernel<<<N_NODES / NPB, 128>>>(x0, x1, x2, out);
}